// round 6
// baseline (speedup 1.0000x reference)
#include <cuda_runtime.h>
#include <cuda_bf16.h>
#include <stdint.h>
#include <math.h>

#define BATCH   8
#define SEQ     4096
#define DIMN    512
#define HEADS   8
#define DHEAD   64
#define WIN     128
#define NW      (SEQ / WIN)
#define NTOK    (BATCH * SEQ)
#define QKVD    (3 * DIMN)
#define FFD     (4 * DIMN)

// ======================= scratch (static device memory) ========================
__device__ float         g_qkv [(size_t)NTOK * QKVD];
__device__ float         g_x1  [(size_t)NTOK * DIMN];
__device__ __nv_bfloat16 g_h_hi [(size_t)NTOK * DIMN];
__device__ __nv_bfloat16 g_h_lo [(size_t)NTOK * DIMN];
__device__ __nv_bfloat16 g_at_hi[(size_t)NTOK * DIMN];
__device__ __nv_bfloat16 g_at_lo[(size_t)NTOK * DIMN];
__device__ __nv_bfloat16 g_f1_hi[(size_t)NTOK * FFD];
__device__ __nv_bfloat16 g_f1_lo[(size_t)NTOK * FFD];
__device__ __nv_bfloat16 g_wqkv_hi[QKVD * DIMN], g_wqkv_lo[QKVD * DIMN];
__device__ __nv_bfloat16 g_wout_hi[DIMN * DIMN], g_wout_lo[DIMN * DIMN];
__device__ __nv_bfloat16 g_wff1_hi[FFD * DIMN],  g_wff1_lo[FFD * DIMN];
__device__ __nv_bfloat16 g_wff2_hi[DIMN * FFD],  g_wff2_lo[DIMN * FFD];

// ============================ helpers ==========================================
__device__ __forceinline__ uint32_t smem_u32(const void* p) {
    uint32_t a;
    asm("{ .reg .u64 t; cvta.to.shared.u64 t, %1; cvt.u32.u64 %0, t; }" : "=r"(a) : "l"(p));
    return a;
}
#define SWZ(o) ((o) ^ (((o) >> 3) & 0x70))   // SW128: stagger 16B chunks per row

__device__ __forceinline__ void cp_async16(uint32_t dst, const void* src) {
    asm volatile("cp.async.cg.shared.global [%0], [%1], 16;" :: "r"(dst), "l"(src));
}
__device__ __forceinline__ void cp_commit() {
    asm volatile("cp.async.commit_group;");
}
template <int N>
__device__ __forceinline__ void cp_wait() {
    asm volatile("cp.async.wait_group %0;" :: "n"(N));
}
__device__ __forceinline__ void ldmatrix_x4(uint32_t& r0, uint32_t& r1,
                                            uint32_t& r2, uint32_t& r3, uint32_t a) {
    asm volatile("ldmatrix.sync.aligned.m8n8.x4.shared.b16 {%0,%1,%2,%3}, [%4];"
                 : "=r"(r0), "=r"(r1), "=r"(r2), "=r"(r3) : "r"(a));
}
__device__ __forceinline__ void mma_bf16(float* c, const uint32_t* a, const uint32_t* b) {
    asm volatile("mma.sync.aligned.m16n8k16.row.col.f32.bf16.bf16.f32 "
                 "{%0,%1,%2,%3}, {%4,%5,%6,%7}, {%8,%9}, {%0,%1,%2,%3};"
                 : "+f"(c[0]), "+f"(c[1]), "+f"(c[2]), "+f"(c[3])
                 : "r"(a[0]), "r"(a[1]), "r"(a[2]), "r"(a[3]), "r"(b[0]), "r"(b[1]));
}
__device__ __forceinline__ void split_bf16(float v, __nv_bfloat16& h, __nv_bfloat16& l) {
    h = __float2bfloat16(v);
    l = __float2bfloat16(v - __bfloat162float(h));
}

// ================= LayerNorm -> bf16 hi/lo split. block = token =================
__global__ __launch_bounds__(128) void ln_kernel(const float* __restrict__ in,
                                                 const float* __restrict__ gamma,
                                                 const float* __restrict__ beta,
                                                 __nv_bfloat16* __restrict__ ohi,
                                                 __nv_bfloat16* __restrict__ olo)
{
    int t = blockIdx.x;
    int tid = threadIdx.x;
    const float4* row = (const float4*)(in + (size_t)t * DIMN);
    float4 v = row[tid];
    float s  = v.x + v.y + v.z + v.w;
    float ss = v.x * v.x + v.y * v.y + v.z * v.z + v.w * v.w;
#pragma unroll
    for (int o = 16; o > 0; o >>= 1) {
        s  += __shfl_xor_sync(0xffffffffu, s, o);
        ss += __shfl_xor_sync(0xffffffffu, ss, o);
    }
    __shared__ float sm[4], sm2[4];
    int w = tid >> 5, lane = tid & 31;
    if (lane == 0) { sm[w] = s; sm2[w] = ss; }
    __syncthreads();
    s  = sm[0] + sm[1] + sm[2] + sm[3];
    ss = sm2[0] + sm2[1] + sm2[2] + sm2[3];
    float mean = s * (1.0f / DIMN);
    float var  = ss * (1.0f / DIMN) - mean * mean;
    float inv  = rsqrtf(var + 1e-5f);
    float4 g = ((const float4*)gamma)[tid];
    float4 b = ((const float4*)beta)[tid];
    float o0 = (v.x - mean) * inv * g.x + b.x;
    float o1 = (v.y - mean) * inv * g.y + b.y;
    float o2 = (v.z - mean) * inv * g.z + b.z;
    float o3 = (v.w - mean) * inv * g.w + b.w;
    __nv_bfloat16 h0, h1, h2, h3, l0, l1, l2, l3;
    split_bf16(o0, h0, l0); split_bf16(o1, h1, l1);
    split_bf16(o2, h2, l2); split_bf16(o3, h3, l3);
    __nv_bfloat162 ph0(h0, h1), ph1(h2, h3), pl0(l0, l1), pl1(l2, l3);
    *(uint2*)(ohi + (size_t)t * DIMN + tid * 4) = make_uint2(*(uint32_t*)&ph0, *(uint32_t*)&ph1);
    *(uint2*)(olo + (size_t)t * DIMN + tid * 4) = make_uint2(*(uint32_t*)&pl0, *(uint32_t*)&pl1);
}

// ================= weight split: fp32 -> bf16 hi/lo =============================
__global__ void split_kernel(const float* __restrict__ in,
                             __nv_bfloat16* __restrict__ hi,
                             __nv_bfloat16* __restrict__ lo, int n4)
{
    int i = blockIdx.x * blockDim.x + threadIdx.x;
    if (i >= n4) return;
    float4 v = ((const float4*)in)[i];
    __nv_bfloat16 h0, h1, h2, h3, l0, l1, l2, l3;
    split_bf16(v.x, h0, l0); split_bf16(v.y, h1, l1);
    split_bf16(v.z, h2, l2); split_bf16(v.w, h3, l3);
    __nv_bfloat162 ph0(h0, h1), ph1(h2, h3), pl0(l0, l1), pl1(l2, l3);
    ((uint2*)hi)[i] = make_uint2(*(uint32_t*)&ph0, *(uint32_t*)&ph1);
    ((uint2*)lo)[i] = make_uint2(*(uint32_t*)&pl0, *(uint32_t*)&pl1);
}

// ========= q/k post: l2norm*scale + rotary (double trig, fp32 phase) ============
__global__ __launch_bounds__(256) void qkpost_kernel(float* __restrict__ qkv,
                                                     const float* __restrict__ qsc,
                                                     const float* __restrict__ ksc)
{
    int t = blockIdx.x;
    int n = t & (SEQ - 1);
    int h = threadIdx.x >> 5;
    int lane = threadIdx.x & 31;

    double invf_d = exp(-(double)(2 * lane) * (9.210340371976184 / 64.0));
    float invf = (float)invf_d;
    float ph = (float)n * invf;
    double sd, cd;
    sincos((double)ph, &sd, &cd);
    float c = (float)cd, s = (float)sd;

    float* base = qkv + (size_t)t * QKVD + h * DHEAD;
    {
        float a = base[lane], b = base[lane + 32];
        float ssq = a * a + b * b;
#pragma unroll
        for (int o = 16; o > 0; o >>= 1) ssq += __shfl_xor_sync(0xffffffffu, ssq, o);
        float inv = 1.0f / fmaxf(sqrtf(ssq), 1e-12f);
        float an = a * inv * qsc[lane];
        float bn = b * inv * qsc[lane + 32];
        base[lane]      = an * c - bn * s;
        base[lane + 32] = bn * c + an * s;
    }
    {
        float* kb = base + DIMN;
        float a = kb[lane], b = kb[lane + 32];
        float ssq = a * a + b * b;
#pragma unroll
        for (int o = 16; o > 0; o >>= 1) ssq += __shfl_xor_sync(0xffffffffu, ssq, o);
        float inv = 1.0f / fmaxf(sqrtf(ssq), 1e-12f);
        float an = a * inv * ksc[lane];
        float bn = b * inv * ksc[lane + 32];
        kb[lane]      = an * c - bn * s;
        kb[lane + 32] = bn * c + an * s;
    }
}

// ====== local-window attention: 2 threads per query (half head-dim each) =======
// 256 threads: thread pair (2i, 2i+1) handles query i; thread owns dims
// [hf*32, hf*32+32). Dot combined with one shfl_xor; softmax state duplicated.
// Lanes loop to the warp-max causal bound with predicated updates so the
// shfl stays uniform. Skipping masked keys == -1e9 fill (exp underflows to 0).
__global__ __launch_bounds__(256) void attn_kernel(const float* __restrict__ qkv,
                                                   __nv_bfloat16* __restrict__ ohi,
                                                   __nv_bfloat16* __restrict__ olo)
{
    __shared__ float sK[64][DHEAD];
    __shared__ float sV[64][DHEAD];

    int w = blockIdx.x, h = blockIdx.y, b = blockIdx.z;
    int tid = threadIdx.x;
    int i  = tid >> 1;          // query row 0..127
    int hf = tid & 1;           // half selector
    int tok0 = b * SEQ + w * WIN;
    int tok  = tok0 + i;

    float q[32];
    {
        const float4* srcQ = (const float4*)(qkv + (size_t)tok * QKVD + h * DHEAD + hf * 32);
#pragma unroll
        for (int d4 = 0; d4 < 8; ++d4) {
            float4 t4 = srcQ[d4];
            q[d4 * 4 + 0] = t4.x; q[d4 * 4 + 1] = t4.y;
            q[d4 * 4 + 2] = t4.z; q[d4 * 4 + 3] = t4.w;
        }
    }

    float acc[32];
#pragma unroll
    for (int d = 0; d < 32; ++d) acc[d] = 0.f;
    float m = -1e30f, l = 0.f;

#pragma unroll 1
    for (int c = 0; c < 4; ++c) {
        if (c < 2 && w == 0) continue;   // uniform across block

        __syncthreads();
        {
            int r  = tid >> 2;                 // 0..63
            int f0 = (tid & 3) * 4;            // float4 quarter
            int ktok = tok0 + c * 64 - WIN + r;
            const float4* sk = (const float4*)(qkv + (size_t)ktok * QKVD + DIMN + h * DHEAD);
            const float4* sv = (const float4*)(qkv + (size_t)ktok * QKVD + 2 * DIMN + h * DHEAD);
            float4* dK = (float4*)&sK[r][0];
            float4* dV = (float4*)&sV[r][0];
#pragma unroll
            for (int f = 0; f < 4; ++f) { dK[f0 + f] = sk[f0 + f]; dV[f0 + f] = sv[f0 + f]; }
        }
        __syncthreads();

        int jmax;
        if (c < 2) jmax = 64;
        else {
            jmax = i - (c - 2) * 64 + 1;
            jmax = jmax < 0 ? 0 : (jmax > 64 ? 64 : jmax);
        }
        int jcap = __reduce_max_sync(0xffffffffu, jmax);

        for (int j = 0; j < jcap; ++j) {
            const float4* kr = (const float4*)&sK[j][hf * 32];
            float s0 = 0.f, s1 = 0.f, s2 = 0.f, s3 = 0.f;
#pragma unroll
            for (int d4 = 0; d4 < 8; ++d4) {
                float4 kv = kr[d4];
                s0 += q[d4 * 4 + 0] * kv.x;
                s1 += q[d4 * 4 + 1] * kv.y;
                s2 += q[d4 * 4 + 2] * kv.z;
                s3 += q[d4 * 4 + 3] * kv.w;
            }
            float sh = (s0 + s1) + (s2 + s3);
            sh += __shfl_xor_sync(0xffffffffu, sh, 1);   // full 64-dim dot
            if (j < jmax) {
                float sc = sh * 8.0f;                    // QK_SCALE
                float mn = fmaxf(m, sc);
                float resc = __expf(m - mn);
                float p    = __expf(sc - mn);
                l = l * resc + p;
                m = mn;
                const float4* vr = (const float4*)&sV[j][hf * 32];
#pragma unroll
                for (int d4 = 0; d4 < 8; ++d4) {
                    float4 vv = vr[d4];
                    acc[d4 * 4 + 0] = acc[d4 * 4 + 0] * resc + p * vv.x;
                    acc[d4 * 4 + 1] = acc[d4 * 4 + 1] * resc + p * vv.y;
                    acc[d4 * 4 + 2] = acc[d4 * 4 + 2] * resc + p * vv.z;
                    acc[d4 * 4 + 3] = acc[d4 * 4 + 3] * resc + p * vv.w;
                }
            }
        }
    }

    float invl = 1.0f / l;
    size_t dstoff = (size_t)tok * DIMN + h * DHEAD + hf * 32;
#pragma unroll
    for (int d4 = 0; d4 < 8; ++d4) {
        float v0 = acc[d4 * 4 + 0] * invl, v1 = acc[d4 * 4 + 1] * invl;
        float v2 = acc[d4 * 4 + 2] * invl, v3 = acc[d4 * 4 + 3] * invl;
        __nv_bfloat16 h0, h1, h2, h3, l0, l1, l2, l3;
        split_bf16(v0, h0, l0); split_bf16(v1, h1, l1);
        split_bf16(v2, h2, l2); split_bf16(v3, h3, l3);
        __nv_bfloat162 ph0(h0, h1), ph1(h2, h3), pl0(l0, l1), pl1(l2, l3);
        *(uint2*)(ohi + dstoff + d4 * 4) = make_uint2(*(uint32_t*)&ph0, *(uint32_t*)&ph1);
        *(uint2*)(olo + dstoff + d4 * 4) = make_uint2(*(uint32_t*)&pl0, *(uint32_t*)&pl1);
    }
}

// ====== HMMA GEMM, bf16x3 split, 128x128 tile, double-buffered cp.async ========
// C[M,N] = A[M,K] @ B[N,K]^T in virtual fp32: Ahi*Bhi + Alo*Bhi + Ahi*Blo.
// 256 threads = 8 warps: warpM = wid&3 (32 rows), warpN = wid>>2 (64 cols).
// 2 smem stages x 4 tiles (Ahi, Alo, Bhi, Blo) of 128x64 bf16 (SW128 rows).
// EPI: 0 fp32 | 1 +bias+resid fp32 | 2 gelu -> bf16 hi/lo | 3 +resid fp32
#define KBLK     64
#define TILE_B   16384
#define STAGE_B  (4 * TILE_B)
#define SM_TOTAL (2 * STAGE_B)

__device__ __forceinline__ float gelu_f(float x)
{
    return 0.5f * x * (1.0f + erff(x * 0.7071067811865476f));
}

template <int EPI>
__global__ __launch_bounds__(256, 1) void gemm_tc(
    const __nv_bfloat16* __restrict__ Ahi, const __nv_bfloat16* __restrict__ Alo,
    const __nv_bfloat16* __restrict__ Bhi, const __nv_bfloat16* __restrict__ Blo,
    int M, int N, int K,
    float* __restrict__ Cf,
    __nv_bfloat16* __restrict__ Chi, __nv_bfloat16* __restrict__ Clo,
    const float* __restrict__ bias, const float* __restrict__ resid)
{
    extern __shared__ char smem[];
    uint32_t sb = smem_u32(smem);
    int tid = threadIdx.x, wid = tid >> 5, lane = tid & 31;
    int warpM = wid & 3, warpN = wid >> 2;
    int bm = blockIdx.y * 128, bn = blockIdx.x * 128;

    float acc[2][8][4];
#pragma unroll
    for (int mi = 0; mi < 2; ++mi)
#pragma unroll
        for (int ni = 0; ni < 8; ++ni)
#pragma unroll
            for (int r = 0; r < 4; ++r) acc[mi][ni][r] = 0.f;

    // ldmatrix lane->address mapping
    int aRow  = lane & 15;
    int aKoff = (lane >> 4) << 3;
    int bRow  = (lane & 7) + ((lane >> 4) << 3);
    int bKoff = ((lane >> 3) & 1) << 3;

    // per-thread load coords (16B granules): 4 per tile
    int ldRow = tid >> 3, ldC16 = tid & 7;     // it-th granule: row ldRow + it*32

    const __nv_bfloat16* srcs[4] = { Ahi, Alo, Bhi, Blo };
    int rb0 = bm, rb1 = bn;

    int kchunks = K / KBLK;

    // ---- prologue: load chunk 0 into stage 0
    {
#pragma unroll
        for (int tile = 0; tile < 4; ++tile) {
            const __nv_bfloat16* src = srcs[tile];
            int rbase = (tile < 2) ? rb0 : rb1;
            uint32_t dstb = sb + tile * TILE_B;
#pragma unroll
            for (int it = 0; it < 4; ++it) {
                int row = ldRow + it * 32;
                cp_async16(dstb + SWZ(row * 128 + ldC16 * 16),
                           src + (size_t)(rbase + row) * K + ldC16 * 8);
            }
        }
        cp_commit();
    }

#pragma unroll 1
    for (int kc = 0; kc < kchunks; ++kc) {
        uint32_t cur = sb + (uint32_t)(kc & 1) * STAGE_B;
        if (kc + 1 < kchunks) {
            // prefetch next chunk into the other stage (freed by prior sync)
            uint32_t nxt = sb + (uint32_t)((kc + 1) & 1) * STAGE_B;
            int k0 = (kc + 1) * KBLK;
#pragma unroll
            for (int tile = 0; tile < 4; ++tile) {
                const __nv_bfloat16* src = srcs[tile];
                int rbase = (tile < 2) ? rb0 : rb1;
                uint32_t dstb = nxt + tile * TILE_B;
#pragma unroll
                for (int it = 0; it < 4; ++it) {
                    int row = ldRow + it * 32;
                    cp_async16(dstb + SWZ(row * 128 + ldC16 * 16),
                               src + (size_t)(rbase + row) * K + k0 + ldC16 * 8);
                }
            }
            cp_commit();
            cp_wait<1>();     // chunk kc complete; next may still be in flight
        } else {
            cp_wait<0>();
        }
        __syncthreads();

#pragma unroll 1
        for (int k16 = 0; k16 < KBLK / 16; ++k16) {
#pragma unroll 1
            for (int term = 0; term < 3; ++term) {
                uint32_t aBase = cur + (term == 1 ? TILE_B : 0);
                uint32_t bBase = cur + 2 * TILE_B + (term == 2 ? TILE_B : 0);
                uint32_t a[2][4], b[8][2];
#pragma unroll
                for (int mi = 0; mi < 2; ++mi) {
                    uint32_t addr = aBase + SWZ((warpM * 32 + mi * 16 + aRow) * 128 +
                                                (k16 * 16 + aKoff) * 2);
                    ldmatrix_x4(a[mi][0], a[mi][1], a[mi][2], a[mi][3], addr);
                }
#pragma unroll
                for (int np = 0; np < 4; ++np) {
                    uint32_t addr = bBase + SWZ((warpN * 64 + np * 16 + bRow) * 128 +
                                                (k16 * 16 + bKoff) * 2);
                    ldmatrix_x4(b[np * 2][0], b[np * 2][1],
                                b[np * 2 + 1][0], b[np * 2 + 1][1], addr);
                }
#pragma unroll
                for (int mi = 0; mi < 2; ++mi)
#pragma unroll
                    for (int ni = 0; ni < 8; ++ni)
                        mma_bf16(acc[mi][ni], a[mi], b[ni]);
            }
        }
        __syncthreads();   // all warps done with 'cur' before it is refilled
    }

    // epilogue
#pragma unroll
    for (int mi = 0; mi < 2; ++mi)
#pragma unroll
        for (int ni = 0; ni < 8; ++ni) {
            int row = bm + warpM * 32 + mi * 16 + (lane >> 2);
            int col = bn + warpN * 64 + ni * 8 + (lane & 3) * 2;
#pragma unroll
            for (int hh = 0; hh < 2; ++hh) {
                int r = row + hh * 8;
                float v0 = acc[mi][ni][hh * 2 + 0];
                float v1 = acc[mi][ni][hh * 2 + 1];
                size_t idx = (size_t)r * N + col;
                if (EPI == 2) {
                    v0 = gelu_f(v0); v1 = gelu_f(v1);
                    __nv_bfloat16 h0, h1, l0, l1;
                    split_bf16(v0, h0, l0); split_bf16(v1, h1, l1);
                    __nv_bfloat162 hp(h0, h1), lp(l0, l1);
                    *(uint32_t*)(Chi + idx) = *(uint32_t*)&hp;
                    *(uint32_t*)(Clo + idx) = *(uint32_t*)&lp;
                } else {
                    if (EPI == 1) {
                        float2 rs = *(const float2*)(resid + idx);
                        v0 += bias[col] + rs.x;
                        v1 += bias[col + 1] + rs.y;
                    } else if (EPI == 3) {
                        float2 rs = *(const float2*)(resid + idx);
                        v0 += rs.x; v1 += rs.y;
                    }
                    *(float2*)(Cf + idx) = make_float2(v0, v1);
                }
            }
        }
}

// ------------------------------- launch ---------------------------------------
extern "C" void kernel_launch(void* const* d_in, const int* in_sizes, int n_in,
                              void* d_out, int out_size)
{
    const float* x       = (const float*)d_in[0];
    const float* w_qkv   = (const float*)d_in[1];
    const float* q_scale = (const float*)d_in[2];
    const float* k_scale = (const float*)d_in[3];
    const float* w_out   = (const float*)d_in[4];
    const float* b_out   = (const float*)d_in[5];
    const float* ln1_g   = (const float*)d_in[6];
    const float* ln1_b   = (const float*)d_in[7];
    const float* ff_ln_g = (const float*)d_in[8];
    const float* ff_ln_b = (const float*)d_in[9];
    const float* w_ff1   = (const float*)d_in[10];
    const float* w_ff2   = (const float*)d_in[11];
    float* out = (float*)d_out;

    float *p_qkv, *p_x1;
    __nv_bfloat16 *p_h_hi, *p_h_lo, *p_at_hi, *p_at_lo, *p_f1_hi, *p_f1_lo;
    __nv_bfloat16 *p_wqkv_hi, *p_wqkv_lo, *p_wout_hi, *p_wout_lo;
    __nv_bfloat16 *p_wff1_hi, *p_wff1_lo, *p_wff2_hi, *p_wff2_lo;
    cudaGetSymbolAddress((void**)&p_qkv, g_qkv);
    cudaGetSymbolAddress((void**)&p_x1, g_x1);
    cudaGetSymbolAddress((void**)&p_h_hi, g_h_hi);
    cudaGetSymbolAddress((void**)&p_h_lo, g_h_lo);
    cudaGetSymbolAddress((void**)&p_at_hi, g_at_hi);
    cudaGetSymbolAddress((void**)&p_at_lo, g_at_lo);
    cudaGetSymbolAddress((void**)&p_f1_hi, g_f1_hi);
    cudaGetSymbolAddress((void**)&p_f1_lo, g_f1_lo);
    cudaGetSymbolAddress((void**)&p_wqkv_hi, g_wqkv_hi);
    cudaGetSymbolAddress((void**)&p_wqkv_lo, g_wqkv_lo);
    cudaGetSymbolAddress((void**)&p_wout_hi, g_wout_hi);
    cudaGetSymbolAddress((void**)&p_wout_lo, g_wout_lo);
    cudaGetSymbolAddress((void**)&p_wff1_hi, g_wff1_hi);
    cudaGetSymbolAddress((void**)&p_wff1_lo, g_wff1_lo);
    cudaGetSymbolAddress((void**)&p_wff2_hi, g_wff2_hi);
    cudaGetSymbolAddress((void**)&p_wff2_lo, g_wff2_lo);

    cudaFuncSetAttribute(gemm_tc<0>, cudaFuncAttributeMaxDynamicSharedMemorySize, SM_TOTAL);
    cudaFuncSetAttribute(gemm_tc<1>, cudaFuncAttributeMaxDynamicSharedMemorySize, SM_TOTAL);
    cudaFuncSetAttribute(gemm_tc<2>, cudaFuncAttributeMaxDynamicSharedMemorySize, SM_TOTAL);
    cudaFuncSetAttribute(gemm_tc<3>, cudaFuncAttributeMaxDynamicSharedMemorySize, SM_TOTAL);

    // weight splits
    split_kernel<<<(QKVD * DIMN / 4 + 255) / 256, 256>>>(w_qkv, p_wqkv_hi, p_wqkv_lo, QKVD * DIMN / 4);
    split_kernel<<<(DIMN * DIMN / 4 + 255) / 256, 256>>>(w_out, p_wout_hi, p_wout_lo, DIMN * DIMN / 4);
    split_kernel<<<(FFD * DIMN / 4 + 255) / 256, 256>>>(w_ff1, p_wff1_hi, p_wff1_lo, FFD * DIMN / 4);
    split_kernel<<<(DIMN * FFD / 4 + 255) / 256, 256>>>(w_ff2, p_wff2_hi, p_wff2_lo, DIMN * FFD / 4);

    // 1) h = LN1(x) -> hi/lo
    ln_kernel<<<NTOK, 128>>>(x, ln1_g, ln1_b, p_h_hi, p_h_lo);

    // 2) qkv = h @ w_qkv^T (fp32 out)
    gemm_tc<0><<<dim3(QKVD / 128, NTOK / 128), 256, SM_TOTAL>>>(
        p_h_hi, p_h_lo, p_wqkv_hi, p_wqkv_lo, NTOK, QKVD, DIMN,
        p_qkv, nullptr, nullptr, nullptr, nullptr);

    // 3) l2norm*scale + rotary (in place)
    qkpost_kernel<<<NTOK, 256>>>(p_qkv, q_scale, k_scale);

    // 4) attention -> hi/lo
    attn_kernel<<<dim3(NW, HEADS, BATCH), 256>>>(p_qkv, p_at_hi, p_at_lo);

    // 5) x1 = x + attn @ w_out^T + b_out
    gemm_tc<1><<<dim3(DIMN / 128, NTOK / 128), 256, SM_TOTAL>>>(
        p_at_hi, p_at_lo, p_wout_hi, p_wout_lo, NTOK, DIMN, DIMN,
        p_x1, nullptr, nullptr, b_out, x);

    // 6) h = LN2(x1) -> hi/lo
    ln_kernel<<<NTOK, 128>>>(p_x1, ff_ln_g, ff_ln_b, p_h_hi, p_h_lo);

    // 7) ff1 = gelu(h @ w_ff1^T) -> hi/lo
    gemm_tc<2><<<dim3(FFD / 128, NTOK / 128), 256, SM_TOTAL>>>(
        p_h_hi, p_h_lo, p_wff1_hi, p_wff1_lo, NTOK, FFD, DIMN,
        nullptr, p_f1_hi, p_f1_lo, nullptr, nullptr);

    // 8) out = x1 + ff1 @ w_ff2^T
    gemm_tc<3><<<dim3(DIMN / 128, NTOK / 128), 256, SM_TOTAL>>>(
        p_f1_hi, p_f1_lo, p_wff2_hi, p_wff2_lo, NTOK, DIMN, FFD,
        out, nullptr, nullptr, nullptr, p_x1);
}

// round 7
// speedup vs baseline: 1.0273x; 1.0273x over previous
#include <cuda_runtime.h>
#include <cuda_bf16.h>
#include <stdint.h>
#include <math.h>

#define BATCH   8
#define SEQ     4096
#define DIMN    512
#define HEADS   8
#define DHEAD   64
#define WIN     128
#define NW      (SEQ / WIN)
#define NTOK    (BATCH * SEQ)
#define QKVD    (3 * DIMN)
#define FFD     (4 * DIMN)

// ======================= scratch (static device memory) ========================
__device__ float         g_qkv [(size_t)NTOK * QKVD];
__device__ float         g_x1  [(size_t)NTOK * DIMN];
__device__ __nv_bfloat16 g_h_hi [(size_t)NTOK * DIMN];
__device__ __nv_bfloat16 g_h_lo [(size_t)NTOK * DIMN];
__device__ __nv_bfloat16 g_at_hi[(size_t)NTOK * DIMN];
__device__ __nv_bfloat16 g_at_lo[(size_t)NTOK * DIMN];
__device__ __nv_bfloat16 g_f1_hi[(size_t)NTOK * FFD];
__device__ __nv_bfloat16 g_f1_lo[(size_t)NTOK * FFD];
__device__ __nv_bfloat16 g_wqkv_hi[QKVD * DIMN], g_wqkv_lo[QKVD * DIMN];
__device__ __nv_bfloat16 g_wout_hi[DIMN * DIMN], g_wout_lo[DIMN * DIMN];
__device__ __nv_bfloat16 g_wff1_hi[FFD * DIMN],  g_wff1_lo[FFD * DIMN];
__device__ __nv_bfloat16 g_wff2_hi[DIMN * FFD],  g_wff2_lo[DIMN * FFD];

// ============================ helpers ==========================================
__device__ __forceinline__ uint32_t smem_u32(const void* p) {
    uint32_t a;
    asm("{ .reg .u64 t; cvta.to.shared.u64 t, %1; cvt.u32.u64 %0, t; }" : "=r"(a) : "l"(p));
    return a;
}
#define SWZ64(o) ((o) ^ (((o) >> 3) & 0x30))   // SW64: 8 rows x 64B atom

__device__ __forceinline__ void cp_async16(uint32_t dst, const void* src) {
    asm volatile("cp.async.cg.shared.global [%0], [%1], 16;" :: "r"(dst), "l"(src));
}
__device__ __forceinline__ void cp_commit() {
    asm volatile("cp.async.commit_group;");
}
template <int N>
__device__ __forceinline__ void cp_wait() {
    asm volatile("cp.async.wait_group %0;" :: "n"(N));
}
__device__ __forceinline__ void ldmatrix_x4(uint32_t& r0, uint32_t& r1,
                                            uint32_t& r2, uint32_t& r3, uint32_t a) {
    asm volatile("ldmatrix.sync.aligned.m8n8.x4.shared.b16 {%0,%1,%2,%3}, [%4];"
                 : "=r"(r0), "=r"(r1), "=r"(r2), "=r"(r3) : "r"(a));
}
__device__ __forceinline__ void mma_bf16(float* c, const uint32_t* a, const uint32_t* b) {
    asm volatile("mma.sync.aligned.m16n8k16.row.col.f32.bf16.bf16.f32 "
                 "{%0,%1,%2,%3}, {%4,%5,%6,%7}, {%8,%9}, {%0,%1,%2,%3};"
                 : "+f"(c[0]), "+f"(c[1]), "+f"(c[2]), "+f"(c[3])
                 : "r"(a[0]), "r"(a[1]), "r"(a[2]), "r"(a[3]), "r"(b[0]), "r"(b[1]));
}
__device__ __forceinline__ void split_bf16(float v, __nv_bfloat16& h, __nv_bfloat16& l) {
    h = __float2bfloat16(v);
    l = __float2bfloat16(v - __bfloat162float(h));
}

// ================= LayerNorm -> bf16 hi/lo split. block = token =================
__global__ __launch_bounds__(128) void ln_kernel(const float* __restrict__ in,
                                                 const float* __restrict__ gamma,
                                                 const float* __restrict__ beta,
                                                 __nv_bfloat16* __restrict__ ohi,
                                                 __nv_bfloat16* __restrict__ olo)
{
    int t = blockIdx.x;
    int tid = threadIdx.x;
    const float4* row = (const float4*)(in + (size_t)t * DIMN);
    float4 v = row[tid];
    float s  = v.x + v.y + v.z + v.w;
    float ss = v.x * v.x + v.y * v.y + v.z * v.z + v.w * v.w;
#pragma unroll
    for (int o = 16; o > 0; o >>= 1) {
        s  += __shfl_xor_sync(0xffffffffu, s, o);
        ss += __shfl_xor_sync(0xffffffffu, ss, o);
    }
    __shared__ float sm[4], sm2[4];
    int w = tid >> 5, lane = tid & 31;
    if (lane == 0) { sm[w] = s; sm2[w] = ss; }
    __syncthreads();
    s  = sm[0] + sm[1] + sm[2] + sm[3];
    ss = sm2[0] + sm2[1] + sm2[2] + sm2[3];
    float mean = s * (1.0f / DIMN);
    float var  = ss * (1.0f / DIMN) - mean * mean;
    float inv  = rsqrtf(var + 1e-5f);
    float4 g = ((const float4*)gamma)[tid];
    float4 b = ((const float4*)beta)[tid];
    float o0 = (v.x - mean) * inv * g.x + b.x;
    float o1 = (v.y - mean) * inv * g.y + b.y;
    float o2 = (v.z - mean) * inv * g.z + b.z;
    float o3 = (v.w - mean) * inv * g.w + b.w;
    __nv_bfloat16 h0, h1, h2, h3, l0, l1, l2, l3;
    split_bf16(o0, h0, l0); split_bf16(o1, h1, l1);
    split_bf16(o2, h2, l2); split_bf16(o3, h3, l3);
    __nv_bfloat162 ph0(h0, h1), ph1(h2, h3), pl0(l0, l1), pl1(l2, l3);
    *(uint2*)(ohi + (size_t)t * DIMN + tid * 4) = make_uint2(*(uint32_t*)&ph0, *(uint32_t*)&ph1);
    *(uint2*)(olo + (size_t)t * DIMN + tid * 4) = make_uint2(*(uint32_t*)&pl0, *(uint32_t*)&pl1);
}

// ================= weight split: fp32 -> bf16 hi/lo =============================
__global__ void split_kernel(const float* __restrict__ in,
                             __nv_bfloat16* __restrict__ hi,
                             __nv_bfloat16* __restrict__ lo, int n4)
{
    int i = blockIdx.x * blockDim.x + threadIdx.x;
    if (i >= n4) return;
    float4 v = ((const float4*)in)[i];
    __nv_bfloat16 h0, h1, h2, h3, l0, l1, l2, l3;
    split_bf16(v.x, h0, l0); split_bf16(v.y, h1, l1);
    split_bf16(v.z, h2, l2); split_bf16(v.w, h3, l3);
    __nv_bfloat162 ph0(h0, h1), ph1(h2, h3), pl0(l0, l1), pl1(l2, l3);
    ((uint2*)hi)[i] = make_uint2(*(uint32_t*)&ph0, *(uint32_t*)&ph1);
    ((uint2*)lo)[i] = make_uint2(*(uint32_t*)&pl0, *(uint32_t*)&pl1);
}

// ========= q/k post: l2norm*scale + rotary (double trig, fp32 phase) ============
__global__ __launch_bounds__(256) void qkpost_kernel(float* __restrict__ qkv,
                                                     const float* __restrict__ qsc,
                                                     const float* __restrict__ ksc)
{
    int t = blockIdx.x;
    int n = t & (SEQ - 1);
    int h = threadIdx.x >> 5;
    int lane = threadIdx.x & 31;

    double invf_d = exp(-(double)(2 * lane) * (9.210340371976184 / 64.0));
    float invf = (float)invf_d;
    float ph = (float)n * invf;
    double sd, cd;
    sincos((double)ph, &sd, &cd);
    float c = (float)cd, s = (float)sd;

    float* base = qkv + (size_t)t * QKVD + h * DHEAD;
    {
        float a = base[lane], b = base[lane + 32];
        float ssq = a * a + b * b;
#pragma unroll
        for (int o = 16; o > 0; o >>= 1) ssq += __shfl_xor_sync(0xffffffffu, ssq, o);
        float inv = 1.0f / fmaxf(sqrtf(ssq), 1e-12f);
        float an = a * inv * qsc[lane];
        float bn = b * inv * qsc[lane + 32];
        base[lane]      = an * c - bn * s;
        base[lane + 32] = bn * c + an * s;
    }
    {
        float* kb = base + DIMN;
        float a = kb[lane], b = kb[lane + 32];
        float ssq = a * a + b * b;
#pragma unroll
        for (int o = 16; o > 0; o >>= 1) ssq += __shfl_xor_sync(0xffffffffu, ssq, o);
        float inv = 1.0f / fmaxf(sqrtf(ssq), 1e-12f);
        float an = a * inv * ksc[lane];
        float bn = b * inv * ksc[lane + 32];
        kb[lane]      = an * c - bn * s;
        kb[lane + 32] = bn * c + an * s;
    }
}

// ====== local-window attention: 2 threads per query (half head-dim each) =======
__global__ __launch_bounds__(256) void attn_kernel(const float* __restrict__ qkv,
                                                   __nv_bfloat16* __restrict__ ohi,
                                                   __nv_bfloat16* __restrict__ olo)
{
    __shared__ float sK[64][DHEAD];
    __shared__ float sV[64][DHEAD];

    int w = blockIdx.x, h = blockIdx.y, b = blockIdx.z;
    int tid = threadIdx.x;
    int i  = tid >> 1;          // query row 0..127
    int hf = tid & 1;           // half selector
    int tok0 = b * SEQ + w * WIN;
    int tok  = tok0 + i;

    float q[32];
    {
        const float4* srcQ = (const float4*)(qkv + (size_t)tok * QKVD + h * DHEAD + hf * 32);
#pragma unroll
        for (int d4 = 0; d4 < 8; ++d4) {
            float4 t4 = srcQ[d4];
            q[d4 * 4 + 0] = t4.x; q[d4 * 4 + 1] = t4.y;
            q[d4 * 4 + 2] = t4.z; q[d4 * 4 + 3] = t4.w;
        }
    }

    float acc[32];
#pragma unroll
    for (int d = 0; d < 32; ++d) acc[d] = 0.f;
    float m = -1e30f, l = 0.f;

#pragma unroll 1
    for (int c = 0; c < 4; ++c) {
        if (c < 2 && w == 0) continue;   // uniform across block

        __syncthreads();
        {
            int r  = tid >> 2;                 // 0..63
            int f0 = (tid & 3) * 4;            // float4 quarter
            int ktok = tok0 + c * 64 - WIN + r;
            const float4* sk = (const float4*)(qkv + (size_t)ktok * QKVD + DIMN + h * DHEAD);
            const float4* sv = (const float4*)(qkv + (size_t)ktok * QKVD + 2 * DIMN + h * DHEAD);
            float4* dK = (float4*)&sK[r][0];
            float4* dV = (float4*)&sV[r][0];
#pragma unroll
            for (int f = 0; f < 4; ++f) { dK[f0 + f] = sk[f0 + f]; dV[f0 + f] = sv[f0 + f]; }
        }
        __syncthreads();

        int jmax;
        if (c < 2) jmax = 64;
        else {
            jmax = i - (c - 2) * 64 + 1;
            jmax = jmax < 0 ? 0 : (jmax > 64 ? 64 : jmax);
        }
        int jcap = __reduce_max_sync(0xffffffffu, jmax);

        for (int j = 0; j < jcap; ++j) {
            const float4* kr = (const float4*)&sK[j][hf * 32];
            float s0 = 0.f, s1 = 0.f, s2 = 0.f, s3 = 0.f;
#pragma unroll
            for (int d4 = 0; d4 < 8; ++d4) {
                float4 kv = kr[d4];
                s0 += q[d4 * 4 + 0] * kv.x;
                s1 += q[d4 * 4 + 1] * kv.y;
                s2 += q[d4 * 4 + 2] * kv.z;
                s3 += q[d4 * 4 + 3] * kv.w;
            }
            float sh = (s0 + s1) + (s2 + s3);
            sh += __shfl_xor_sync(0xffffffffu, sh, 1);   // full 64-dim dot
            if (j < jmax) {
                float sc = sh * 8.0f;                    // QK_SCALE
                float mn = fmaxf(m, sc);
                float resc = __expf(m - mn);
                float p    = __expf(sc - mn);
                l = l * resc + p;
                m = mn;
                const float4* vr = (const float4*)&sV[j][hf * 32];
#pragma unroll
                for (int d4 = 0; d4 < 8; ++d4) {
                    float4 vv = vr[d4];
                    acc[d4 * 4 + 0] = acc[d4 * 4 + 0] * resc + p * vv.x;
                    acc[d4 * 4 + 1] = acc[d4 * 4 + 1] * resc + p * vv.y;
                    acc[d4 * 4 + 2] = acc[d4 * 4 + 2] * resc + p * vv.z;
                    acc[d4 * 4 + 3] = acc[d4 * 4 + 3] * resc + p * vv.w;
                }
            }
        }
    }

    float invl = 1.0f / l;
    size_t dstoff = (size_t)tok * DIMN + h * DHEAD + hf * 32;
#pragma unroll
    for (int d4 = 0; d4 < 8; ++d4) {
        float v0 = acc[d4 * 4 + 0] * invl, v1 = acc[d4 * 4 + 1] * invl;
        float v2 = acc[d4 * 4 + 2] * invl, v3 = acc[d4 * 4 + 3] * invl;
        __nv_bfloat16 h0, h1, h2, h3, l0, l1, l2, l3;
        split_bf16(v0, h0, l0); split_bf16(v1, h1, l1);
        split_bf16(v2, h2, l2); split_bf16(v3, h3, l3);
        __nv_bfloat162 ph0(h0, h1), ph1(h2, h3), pl0(l0, l1), pl1(l2, l3);
        *(uint2*)(ohi + dstoff + d4 * 4) = make_uint2(*(uint32_t*)&ph0, *(uint32_t*)&ph1);
        *(uint2*)(olo + dstoff + d4 * 4) = make_uint2(*(uint32_t*)&pl0, *(uint32_t*)&pl1);
    }
}

// == HMMA GEMM, bf16x3 split, 128x128 tile, 2-stage cp.async + 2 CTAs/SM ========
// C[M,N] = A[M,K] @ B[N,K]^T in virtual fp32: Ahi*Bhi + Alo*Bhi + Ahi*Blo.
// K-chunk 32 -> tile 128x32 bf16 = 8KB (64B rows, SW64 swizzle); stage = 32KB;
// 2 stages = 64KB smem -> 2 CTAs/SM (cross-CTA overlap) AND intra-CTA prefetch.
// EPI: 0 fp32 | 1 +bias+resid fp32 | 2 gelu -> bf16 hi/lo | 3 +resid fp32
#define KBLK     32
#define TILE_B   8192
#define STAGE_B  (4 * TILE_B)
#define SM_TOTAL (2 * STAGE_B)

__device__ __forceinline__ float gelu_f(float x)
{
    return 0.5f * x * (1.0f + erff(x * 0.7071067811865476f));
}

template <int EPI>
__global__ __launch_bounds__(256, 2) void gemm_tc(
    const __nv_bfloat16* __restrict__ Ahi, const __nv_bfloat16* __restrict__ Alo,
    const __nv_bfloat16* __restrict__ Bhi, const __nv_bfloat16* __restrict__ Blo,
    int M, int N, int K,
    float* __restrict__ Cf,
    __nv_bfloat16* __restrict__ Chi, __nv_bfloat16* __restrict__ Clo,
    const float* __restrict__ bias, const float* __restrict__ resid)
{
    extern __shared__ char smem[];
    uint32_t sb = smem_u32(smem);
    int tid = threadIdx.x, wid = tid >> 5, lane = tid & 31;
    int warpM = wid & 3, warpN = wid >> 2;
    int bm = blockIdx.y * 128, bn = blockIdx.x * 128;

    float acc[2][8][4];
#pragma unroll
    for (int mi = 0; mi < 2; ++mi)
#pragma unroll
        for (int ni = 0; ni < 8; ++ni)
#pragma unroll
            for (int r = 0; r < 4; ++r) acc[mi][ni][r] = 0.f;

    // ldmatrix lane->address mapping (element coords within tile, 64B rows)
    int aRow  = lane & 15;
    int aKoff = (lane >> 4) << 3;
    int bRow  = (lane & 7) + ((lane >> 4) << 3);
    int bKoff = ((lane >> 3) & 1) << 3;

    // per-thread load coords: 2 x 16B granules per tile
    int ldRow = tid >> 2, ldC16 = tid & 3;     // it-th granule: row ldRow + it*64

    const __nv_bfloat16* srcs[4] = { Ahi, Alo, Bhi, Blo };
    int rb0 = bm, rb1 = bn;

    int kchunks = K / KBLK;

    // ---- prologue: chunk 0 -> stage 0
    {
#pragma unroll
        for (int tile = 0; tile < 4; ++tile) {
            const __nv_bfloat16* src = srcs[tile];
            int rbase = (tile < 2) ? rb0 : rb1;
            uint32_t dstb = sb + tile * TILE_B;
#pragma unroll
            for (int it = 0; it < 2; ++it) {
                int row = ldRow + it * 64;
                cp_async16(dstb + SWZ64(row * 64 + ldC16 * 16),
                           src + (size_t)(rbase + row) * K + ldC16 * 8);
            }
        }
        cp_commit();
    }

#pragma unroll 1
    for (int kc = 0; kc < kchunks; ++kc) {
        uint32_t cur = sb + (uint32_t)(kc & 1) * STAGE_B;
        if (kc + 1 < kchunks) {
            uint32_t nxt = sb + (uint32_t)((kc + 1) & 1) * STAGE_B;
            int k0 = (kc + 1) * KBLK;
#pragma unroll
            for (int tile = 0; tile < 4; ++tile) {
                const __nv_bfloat16* src = srcs[tile];
                int rbase = (tile < 2) ? rb0 : rb1;
                uint32_t dstb = nxt + tile * TILE_B;
#pragma unroll
                for (int it = 0; it < 2; ++it) {
                    int row = ldRow + it * 64;
                    cp_async16(dstb + SWZ64(row * 64 + ldC16 * 16),
                               src + (size_t)(rbase + row) * K + k0 + ldC16 * 8);
                }
            }
            cp_commit();
            cp_wait<1>();     // chunk kc complete; prefetch may still fly
        } else {
            cp_wait<0>();
        }
        __syncthreads();

#pragma unroll
        for (int k16 = 0; k16 < KBLK / 16; ++k16) {
#pragma unroll 1
            for (int term = 0; term < 3; ++term) {
                uint32_t aBase = cur + (term == 1 ? TILE_B : 0);
                uint32_t bBase = cur + 2 * TILE_B + (term == 2 ? TILE_B : 0);
                uint32_t a[2][4], b[8][2];
#pragma unroll
                for (int mi = 0; mi < 2; ++mi) {
                    uint32_t addr = aBase + SWZ64((warpM * 32 + mi * 16 + aRow) * 64 +
                                                  (k16 * 16 + aKoff) * 2);
                    ldmatrix_x4(a[mi][0], a[mi][1], a[mi][2], a[mi][3], addr);
                }
#pragma unroll
                for (int np = 0; np < 4; ++np) {
                    uint32_t addr = bBase + SWZ64((warpN * 64 + np * 16 + bRow) * 64 +
                                                  (k16 * 16 + bKoff) * 2);
                    ldmatrix_x4(b[np * 2][0], b[np * 2][1],
                                b[np * 2 + 1][0], b[np * 2 + 1][1], addr);
                }
#pragma unroll
                for (int mi = 0; mi < 2; ++mi)
#pragma unroll
                    for (int ni = 0; ni < 8; ++ni)
                        mma_bf16(acc[mi][ni], a[mi], b[ni]);
            }
        }
        __syncthreads();   // all warps done with 'cur' before refill
    }

    // epilogue
#pragma unroll
    for (int mi = 0; mi < 2; ++mi)
#pragma unroll
        for (int ni = 0; ni < 8; ++ni) {
            int row = bm + warpM * 32 + mi * 16 + (lane >> 2);
            int col = bn + warpN * 64 + ni * 8 + (lane & 3) * 2;
#pragma unroll
            for (int hh = 0; hh < 2; ++hh) {
                int r = row + hh * 8;
                float v0 = acc[mi][ni][hh * 2 + 0];
                float v1 = acc[mi][ni][hh * 2 + 1];
                size_t idx = (size_t)r * N + col;
                if (EPI == 2) {
                    v0 = gelu_f(v0); v1 = gelu_f(v1);
                    __nv_bfloat16 h0, h1, l0, l1;
                    split_bf16(v0, h0, l0); split_bf16(v1, h1, l1);
                    __nv_bfloat162 hp(h0, h1), lp(l0, l1);
                    *(uint32_t*)(Chi + idx) = *(uint32_t*)&hp;
                    *(uint32_t*)(Clo + idx) = *(uint32_t*)&lp;
                } else {
                    if (EPI == 1) {
                        float2 rs = *(const float2*)(resid + idx);
                        v0 += bias[col] + rs.x;
                        v1 += bias[col + 1] + rs.y;
                    } else if (EPI == 3) {
                        float2 rs = *(const float2*)(resid + idx);
                        v0 += rs.x; v1 += rs.y;
                    }
                    *(float2*)(Cf + idx) = make_float2(v0, v1);
                }
            }
        }
}

// ------------------------------- launch ---------------------------------------
extern "C" void kernel_launch(void* const* d_in, const int* in_sizes, int n_in,
                              void* d_out, int out_size)
{
    const float* x       = (const float*)d_in[0];
    const float* w_qkv   = (const float*)d_in[1];
    const float* q_scale = (const float*)d_in[2];
    const float* k_scale = (const float*)d_in[3];
    const float* w_out   = (const float*)d_in[4];
    const float* b_out   = (const float*)d_in[5];
    const float* ln1_g   = (const float*)d_in[6];
    const float* ln1_b   = (const float*)d_in[7];
    const float* ff_ln_g = (const float*)d_in[8];
    const float* ff_ln_b = (const float*)d_in[9];
    const float* w_ff1   = (const float*)d_in[10];
    const float* w_ff2   = (const float*)d_in[11];
    float* out = (float*)d_out;

    float *p_qkv, *p_x1;
    __nv_bfloat16 *p_h_hi, *p_h_lo, *p_at_hi, *p_at_lo, *p_f1_hi, *p_f1_lo;
    __nv_bfloat16 *p_wqkv_hi, *p_wqkv_lo, *p_wout_hi, *p_wout_lo;
    __nv_bfloat16 *p_wff1_hi, *p_wff1_lo, *p_wff2_hi, *p_wff2_lo;
    cudaGetSymbolAddress((void**)&p_qkv, g_qkv);
    cudaGetSymbolAddress((void**)&p_x1, g_x1);
    cudaGetSymbolAddress((void**)&p_h_hi, g_h_hi);
    cudaGetSymbolAddress((void**)&p_h_lo, g_h_lo);
    cudaGetSymbolAddress((void**)&p_at_hi, g_at_hi);
    cudaGetSymbolAddress((void**)&p_at_lo, g_at_lo);
    cudaGetSymbolAddress((void**)&p_f1_hi, g_f1_hi);
    cudaGetSymbolAddress((void**)&p_f1_lo, g_f1_lo);
    cudaGetSymbolAddress((void**)&p_wqkv_hi, g_wqkv_hi);
    cudaGetSymbolAddress((void**)&p_wqkv_lo, g_wqkv_lo);
    cudaGetSymbolAddress((void**)&p_wout_hi, g_wout_hi);
    cudaGetSymbolAddress((void**)&p_wout_lo, g_wout_lo);
    cudaGetSymbolAddress((void**)&p_wff1_hi, g_wff1_hi);
    cudaGetSymbolAddress((void**)&p_wff1_lo, g_wff1_lo);
    cudaGetSymbolAddress((void**)&p_wff2_hi, g_wff2_hi);
    cudaGetSymbolAddress((void**)&p_wff2_lo, g_wff2_lo);

    cudaFuncSetAttribute(gemm_tc<0>, cudaFuncAttributeMaxDynamicSharedMemorySize, SM_TOTAL);
    cudaFuncSetAttribute(gemm_tc<1>, cudaFuncAttributeMaxDynamicSharedMemorySize, SM_TOTAL);
    cudaFuncSetAttribute(gemm_tc<2>, cudaFuncAttributeMaxDynamicSharedMemorySize, SM_TOTAL);
    cudaFuncSetAttribute(gemm_tc<3>, cudaFuncAttributeMaxDynamicSharedMemorySize, SM_TOTAL);

    // weight splits
    split_kernel<<<(QKVD * DIMN / 4 + 255) / 256, 256>>>(w_qkv, p_wqkv_hi, p_wqkv_lo, QKVD * DIMN / 4);
    split_kernel<<<(DIMN * DIMN / 4 + 255) / 256, 256>>>(w_out, p_wout_hi, p_wout_lo, DIMN * DIMN / 4);
    split_kernel<<<(FFD * DIMN / 4 + 255) / 256, 256>>>(w_ff1, p_wff1_hi, p_wff1_lo, FFD * DIMN / 4);
    split_kernel<<<(DIMN * FFD / 4 + 255) / 256, 256>>>(w_ff2, p_wff2_hi, p_wff2_lo, DIMN * FFD / 4);

    // 1) h = LN1(x) -> hi/lo
    ln_kernel<<<NTOK, 128>>>(x, ln1_g, ln1_b, p_h_hi, p_h_lo);

    // 2) qkv = h @ w_qkv^T (fp32 out)
    gemm_tc<0><<<dim3(QKVD / 128, NTOK / 128), 256, SM_TOTAL>>>(
        p_h_hi, p_h_lo, p_wqkv_hi, p_wqkv_lo, NTOK, QKVD, DIMN,
        p_qkv, nullptr, nullptr, nullptr, nullptr);

    // 3) l2norm*scale + rotary (in place)
    qkpost_kernel<<<NTOK, 256>>>(p_qkv, q_scale, k_scale);

    // 4) attention -> hi/lo
    attn_kernel<<<dim3(NW, HEADS, BATCH), 256>>>(p_qkv, p_at_hi, p_at_lo);

    // 5) x1 = x + attn @ w_out^T + b_out
    gemm_tc<1><<<dim3(DIMN / 128, NTOK / 128), 256, SM_TOTAL>>>(
        p_at_hi, p_at_lo, p_wout_hi, p_wout_lo, NTOK, DIMN, DIMN,
        p_x1, nullptr, nullptr, b_out, x);

    // 6) h = LN2(x1) -> hi/lo
    ln_kernel<<<NTOK, 128>>>(p_x1, ff_ln_g, ff_ln_b, p_h_hi, p_h_lo);

    // 7) ff1 = gelu(h @ w_ff1^T) -> hi/lo
    gemm_tc<2><<<dim3(FFD / 128, NTOK / 128), 256, SM_TOTAL>>>(
        p_h_hi, p_h_lo, p_wff1_hi, p_wff1_lo, NTOK, FFD, DIMN,
        nullptr, p_f1_hi, p_f1_lo, nullptr, nullptr);

    // 8) out = x1 + ff1 @ w_ff2^T
    gemm_tc<3><<<dim3(DIMN / 128, NTOK / 128), 256, SM_TOTAL>>>(
        p_f1_hi, p_f1_lo, p_wff2_hi, p_wff2_lo, NTOK, DIMN, FFD,
        out, nullptr, nullptr, nullptr, p_x1);
}

// round 8
// speedup vs baseline: 1.0742x; 1.0457x over previous
#include <cuda_runtime.h>
#include <cuda_bf16.h>
#include <stdint.h>
#include <math.h>

#define BATCH   8
#define SEQ     4096
#define DIMN    512
#define HEADS   8
#define DHEAD   64
#define WIN     128
#define NW      (SEQ / WIN)
#define NTOK    (BATCH * SEQ)
#define QKVD    (3 * DIMN)
#define FFD     (4 * DIMN)

// ======================= scratch (static device memory) ========================
__device__ float         g_qkv [(size_t)NTOK * QKVD];
__device__ float         g_x1  [(size_t)NTOK * DIMN];
__device__ __nv_bfloat16 g_h_hi [(size_t)NTOK * DIMN];
__device__ __nv_bfloat16 g_h_lo [(size_t)NTOK * DIMN];
__device__ __nv_bfloat16 g_at_hi[(size_t)NTOK * DIMN];
__device__ __nv_bfloat16 g_at_lo[(size_t)NTOK * DIMN];
__device__ __nv_bfloat16 g_f1_hi[(size_t)NTOK * FFD];
__device__ __nv_bfloat16 g_f1_lo[(size_t)NTOK * FFD];
__device__ __nv_bfloat16 g_wqkv_hi[QKVD * DIMN], g_wqkv_lo[QKVD * DIMN];
__device__ __nv_bfloat16 g_wout_hi[DIMN * DIMN], g_wout_lo[DIMN * DIMN];
__device__ __nv_bfloat16 g_wff1_hi[FFD * DIMN],  g_wff1_lo[FFD * DIMN];
__device__ __nv_bfloat16 g_wff2_hi[DIMN * FFD],  g_wff2_lo[DIMN * FFD];

// ============================ helpers ==========================================
__device__ __forceinline__ uint32_t smem_u32(const void* p) {
    uint32_t a;
    asm("{ .reg .u64 t; cvta.to.shared.u64 t, %1; cvt.u32.u64 %0, t; }" : "=r"(a) : "l"(p));
    return a;
}
#define SWZ(o) ((o) ^ (((o) >> 3) & 0x70))   // SW128: stagger 16B chunks per row

__device__ __forceinline__ void cp_async16(uint32_t dst, const void* src) {
    asm volatile("cp.async.cg.shared.global [%0], [%1], 16;" :: "r"(dst), "l"(src));
}
__device__ __forceinline__ void cp_commit_wait() {
    asm volatile("cp.async.commit_group;");
    asm volatile("cp.async.wait_group 0;");
}
__device__ __forceinline__ void ldmatrix_x4(uint32_t& r0, uint32_t& r1,
                                            uint32_t& r2, uint32_t& r3, uint32_t a) {
    asm volatile("ldmatrix.sync.aligned.m8n8.x4.shared.b16 {%0,%1,%2,%3}, [%4];"
                 : "=r"(r0), "=r"(r1), "=r"(r2), "=r"(r3) : "r"(a));
}
__device__ __forceinline__ void mma_bf16(float* c, const uint32_t* a, const uint32_t* b) {
    asm volatile("mma.sync.aligned.m16n8k16.row.col.f32.bf16.bf16.f32 "
                 "{%0,%1,%2,%3}, {%4,%5,%6,%7}, {%8,%9}, {%0,%1,%2,%3};"
                 : "+f"(c[0]), "+f"(c[1]), "+f"(c[2]), "+f"(c[3])
                 : "r"(a[0]), "r"(a[1]), "r"(a[2]), "r"(a[3]), "r"(b[0]), "r"(b[1]));
}
__device__ __forceinline__ void split_bf16(float v, __nv_bfloat16& h, __nv_bfloat16& l) {
    h = __float2bfloat16(v);
    l = __float2bfloat16(v - __bfloat162float(h));
}

// ================= LayerNorm -> bf16 hi/lo split. block = token =================
__global__ __launch_bounds__(128) void ln_kernel(const float* __restrict__ in,
                                                 const float* __restrict__ gamma,
                                                 const float* __restrict__ beta,
                                                 __nv_bfloat16* __restrict__ ohi,
                                                 __nv_bfloat16* __restrict__ olo)
{
    int t = blockIdx.x;
    int tid = threadIdx.x;
    const float4* row = (const float4*)(in + (size_t)t * DIMN);
    float4 v = row[tid];
    float s  = v.x + v.y + v.z + v.w;
    float ss = v.x * v.x + v.y * v.y + v.z * v.z + v.w * v.w;
#pragma unroll
    for (int o = 16; o > 0; o >>= 1) {
        s  += __shfl_xor_sync(0xffffffffu, s, o);
        ss += __shfl_xor_sync(0xffffffffu, ss, o);
    }
    __shared__ float sm[4], sm2[4];
    int w = tid >> 5, lane = tid & 31;
    if (lane == 0) { sm[w] = s; sm2[w] = ss; }
    __syncthreads();
    s  = sm[0] + sm[1] + sm[2] + sm[3];
    ss = sm2[0] + sm2[1] + sm2[2] + sm2[3];
    float mean = s * (1.0f / DIMN);
    float var  = ss * (1.0f / DIMN) - mean * mean;
    float inv  = rsqrtf(var + 1e-5f);
    float4 g = ((const float4*)gamma)[tid];
    float4 b = ((const float4*)beta)[tid];
    float o0 = (v.x - mean) * inv * g.x + b.x;
    float o1 = (v.y - mean) * inv * g.y + b.y;
    float o2 = (v.z - mean) * inv * g.z + b.z;
    float o3 = (v.w - mean) * inv * g.w + b.w;
    __nv_bfloat16 h0, h1, h2, h3, l0, l1, l2, l3;
    split_bf16(o0, h0, l0); split_bf16(o1, h1, l1);
    split_bf16(o2, h2, l2); split_bf16(o3, h3, l3);
    __nv_bfloat162 ph0(h0, h1), ph1(h2, h3), pl0(l0, l1), pl1(l2, l3);
    *(uint2*)(ohi + (size_t)t * DIMN + tid * 4) = make_uint2(*(uint32_t*)&ph0, *(uint32_t*)&ph1);
    *(uint2*)(olo + (size_t)t * DIMN + tid * 4) = make_uint2(*(uint32_t*)&pl0, *(uint32_t*)&pl1);
}

// ================= weight split: fp32 -> bf16 hi/lo =============================
__global__ void split_kernel(const float* __restrict__ in,
                             __nv_bfloat16* __restrict__ hi,
                             __nv_bfloat16* __restrict__ lo, int n4)
{
    int i = blockIdx.x * blockDim.x + threadIdx.x;
    if (i >= n4) return;
    float4 v = ((const float4*)in)[i];
    __nv_bfloat16 h0, h1, h2, h3, l0, l1, l2, l3;
    split_bf16(v.x, h0, l0); split_bf16(v.y, h1, l1);
    split_bf16(v.z, h2, l2); split_bf16(v.w, h3, l3);
    __nv_bfloat162 ph0(h0, h1), ph1(h2, h3), pl0(l0, l1), pl1(l2, l3);
    ((uint2*)hi)[i] = make_uint2(*(uint32_t*)&ph0, *(uint32_t*)&ph1);
    ((uint2*)lo)[i] = make_uint2(*(uint32_t*)&pl0, *(uint32_t*)&pl1);
}

// ========= q/k post: l2norm*scale + rotary (double trig, fp32 phase) ============
__global__ __launch_bounds__(256) void qkpost_kernel(float* __restrict__ qkv,
                                                     const float* __restrict__ qsc,
                                                     const float* __restrict__ ksc)
{
    int t = blockIdx.x;
    int n = t & (SEQ - 1);
    int h = threadIdx.x >> 5;
    int lane = threadIdx.x & 31;

    double invf_d = exp(-(double)(2 * lane) * (9.210340371976184 / 64.0));
    float invf = (float)invf_d;
    float ph = (float)n * invf;
    double sd, cd;
    sincos((double)ph, &sd, &cd);
    float c = (float)cd, s = (float)sd;

    float* base = qkv + (size_t)t * QKVD + h * DHEAD;
    {
        float a = base[lane], b = base[lane + 32];
        float ssq = a * a + b * b;
#pragma unroll
        for (int o = 16; o > 0; o >>= 1) ssq += __shfl_xor_sync(0xffffffffu, ssq, o);
        float inv = 1.0f / fmaxf(sqrtf(ssq), 1e-12f);
        float an = a * inv * qsc[lane];
        float bn = b * inv * qsc[lane + 32];
        base[lane]      = an * c - bn * s;
        base[lane + 32] = bn * c + an * s;
    }
    {
        float* kb = base + DIMN;
        float a = kb[lane], b = kb[lane + 32];
        float ssq = a * a + b * b;
#pragma unroll
        for (int o = 16; o > 0; o >>= 1) ssq += __shfl_xor_sync(0xffffffffu, ssq, o);
        float inv = 1.0f / fmaxf(sqrtf(ssq), 1e-12f);
        float an = a * inv * ksc[lane];
        float bn = b * inv * ksc[lane + 32];
        kb[lane]      = an * c - bn * s;
        kb[lane + 32] = bn * c + an * s;
    }
}

// ====== local-window attention (R5 config: 128 threads, thread = query row) ====
__global__ __launch_bounds__(128) void attn_kernel(const float* __restrict__ qkv,
                                                   __nv_bfloat16* __restrict__ ohi,
                                                   __nv_bfloat16* __restrict__ olo)
{
    __shared__ float sK[64][DHEAD];
    __shared__ float sV[64][DHEAD];

    int w = blockIdx.x, h = blockIdx.y, b = blockIdx.z;
    int i = threadIdx.x;
    int tok0 = b * SEQ + w * WIN;
    int tok  = tok0 + i;

    float q[DHEAD];
    {
        const float4* srcQ = (const float4*)(qkv + (size_t)tok * QKVD + h * DHEAD);
#pragma unroll
        for (int d4 = 0; d4 < 16; ++d4) {
            float4 t4 = srcQ[d4];
            q[d4 * 4 + 0] = t4.x; q[d4 * 4 + 1] = t4.y;
            q[d4 * 4 + 2] = t4.z; q[d4 * 4 + 3] = t4.w;
        }
    }

    float acc[DHEAD];
#pragma unroll
    for (int d = 0; d < DHEAD; ++d) acc[d] = 0.f;
    float m = -1e30f, l = 0.f;

#pragma unroll 1
    for (int c = 0; c < 4; ++c) {
        if (c < 2 && w == 0) continue;

        __syncthreads();
        {
            int r  = i >> 1;
            int f0 = (i & 1) * 8;
            int ktok = tok0 + c * 64 - WIN + r;
            const float4* sk = (const float4*)(qkv + (size_t)ktok * QKVD + DIMN + h * DHEAD);
            const float4* sv = (const float4*)(qkv + (size_t)ktok * QKVD + 2 * DIMN + h * DHEAD);
            float4* dK = (float4*)&sK[r][0];
            float4* dV = (float4*)&sV[r][0];
#pragma unroll
            for (int f = 0; f < 8; ++f) { dK[f0 + f] = sk[f0 + f]; dV[f0 + f] = sv[f0 + f]; }
        }
        __syncthreads();

        int jmax;
        if (c < 2) jmax = 64;
        else {
            jmax = i - (c - 2) * 64 + 1;
            jmax = jmax < 0 ? 0 : (jmax > 64 ? 64 : jmax);
        }
        for (int j = 0; j < jmax; ++j) {
            const float4* kr = (const float4*)&sK[j][0];
            float s0 = 0.f, s1 = 0.f, s2 = 0.f, s3 = 0.f;
#pragma unroll
            for (int d4 = 0; d4 < 16; ++d4) {
                float4 kv = kr[d4];
                s0 += q[d4 * 4 + 0] * kv.x;
                s1 += q[d4 * 4 + 1] * kv.y;
                s2 += q[d4 * 4 + 2] * kv.z;
                s3 += q[d4 * 4 + 3] * kv.w;
            }
            float sc = ((s0 + s1) + (s2 + s3)) * 8.0f;
            float mn = fmaxf(m, sc);
            float resc = __expf(m - mn);
            float p    = __expf(sc - mn);
            l = l * resc + p;
            m = mn;
            const float4* vr = (const float4*)&sV[j][0];
#pragma unroll
            for (int d4 = 0; d4 < 16; ++d4) {
                float4 vv = vr[d4];
                acc[d4 * 4 + 0] = acc[d4 * 4 + 0] * resc + p * vv.x;
                acc[d4 * 4 + 1] = acc[d4 * 4 + 1] * resc + p * vv.y;
                acc[d4 * 4 + 2] = acc[d4 * 4 + 2] * resc + p * vv.z;
                acc[d4 * 4 + 3] = acc[d4 * 4 + 3] * resc + p * vv.w;
            }
        }
    }

    float invl = 1.0f / l;
    size_t dstoff = (size_t)tok * DIMN + h * DHEAD;
#pragma unroll
    for (int d4 = 0; d4 < 16; ++d4) {
        float v0 = acc[d4 * 4 + 0] * invl, v1 = acc[d4 * 4 + 1] * invl;
        float v2 = acc[d4 * 4 + 2] * invl, v3 = acc[d4 * 4 + 3] * invl;
        __nv_bfloat16 h0, h1, h2, h3, l0, l1, l2, l3;
        split_bf16(v0, h0, l0); split_bf16(v1, h1, l1);
        split_bf16(v2, h2, l2); split_bf16(v3, h3, l3);
        __nv_bfloat162 ph0(h0, h1), ph1(h2, h3), pl0(l0, l1), pl1(l2, l3);
        *(uint2*)(ohi + dstoff + d4 * 4) = make_uint2(*(uint32_t*)&ph0, *(uint32_t*)&ph1);
        *(uint2*)(olo + dstoff + d4 * 4) = make_uint2(*(uint32_t*)&pl0, *(uint32_t*)&pl1);
    }
}

// ====== HMMA GEMM, bf16x3 split, 128x128 tile, fragment reuse across terms =====
// C[M,N] = A[M,K] @ B[N,K]^T in virtual fp32: Ahi*Bhi + Alo*Bhi + Ahi*Blo.
// R5 config (KBLK=64, SW128, single buffer, 2 CTAs/SM) + per-k16 fragments
// loaded ONCE and reused across the 3 terms: 12 ldmatrix/warp/k16 instead of 18
// (smem crossbar was the binding pipe: 576 cyc reads vs 422 cyc HMMA per k16).
// EPI: 0 fp32 | 1 +bias+resid fp32 | 2 gelu -> bf16 hi/lo | 3 +resid fp32
#define KBLK     64
#define TILE_B   16384
#define SM_TOTAL (4 * TILE_B)

__device__ __forceinline__ float gelu_f(float x)
{
    return 0.5f * x * (1.0f + erff(x * 0.7071067811865476f));
}

template <int EPI>
__global__ __launch_bounds__(256, 2) void gemm_tc(
    const __nv_bfloat16* __restrict__ Ahi, const __nv_bfloat16* __restrict__ Alo,
    const __nv_bfloat16* __restrict__ Bhi, const __nv_bfloat16* __restrict__ Blo,
    int M, int N, int K,
    float* __restrict__ Cf,
    __nv_bfloat16* __restrict__ Chi, __nv_bfloat16* __restrict__ Clo,
    const float* __restrict__ bias, const float* __restrict__ resid)
{
    extern __shared__ char smem[];
    uint32_t sb = smem_u32(smem);
    int tid = threadIdx.x, wid = tid >> 5, lane = tid & 31;
    int warpM = wid & 3, warpN = wid >> 2;
    int bm = blockIdx.y * 128, bn = blockIdx.x * 128;

    float acc[2][8][4];
#pragma unroll
    for (int mi = 0; mi < 2; ++mi)
#pragma unroll
        for (int ni = 0; ni < 8; ++ni)
#pragma unroll
            for (int r = 0; r < 4; ++r) acc[mi][ni][r] = 0.f;

    // ldmatrix lane->address mapping
    int aRow  = lane & 15;
    int aKoff = (lane >> 4) << 3;
    int bRow  = (lane & 7) + ((lane >> 4) << 3);
    int bKoff = ((lane >> 3) & 1) << 3;

    int kchunks = K / KBLK;
#pragma unroll 1
    for (int kc = 0; kc < kchunks; ++kc) {
        int k0 = kc * KBLK;
        __syncthreads();
        // fill 4 tiles via cp.async (each thread: 16 x 16B)
#pragma unroll
        for (int tile = 0; tile < 4; ++tile) {
            const __nv_bfloat16* src = (tile == 0) ? Ahi : (tile == 1) ? Alo
                                      : (tile == 2) ? Bhi : Blo;
            int rbase = (tile < 2) ? bm : bn;
            uint32_t dstb = sb + tile * TILE_B;
#pragma unroll
            for (int it = 0; it < 4; ++it) {
                int idx = tid + it * 256;
                int row = idx >> 3, c16 = idx & 7;
                cp_async16(dstb + SWZ(row * 128 + c16 * 16),
                           src + (size_t)(rbase + row) * K + k0 + c16 * 8);
            }
        }
        cp_commit_wait();
        __syncthreads();

#pragma unroll 1
        for (int k16 = 0; k16 < KBLK / 16; ++k16) {
            uint32_t aOff = SWZ((warpM * 32 + aRow) * 128 + (k16 * 16 + aKoff) * 2);
            uint32_t aOff2 = SWZ((warpM * 32 + 16 + aRow) * 128 + (k16 * 16 + aKoff) * 2);
            uint32_t ah[2][4], bh[8][2], bl[8][2];

            // --- load Ahi, Bhi fragments
            ldmatrix_x4(ah[0][0], ah[0][1], ah[0][2], ah[0][3], sb + aOff);
            ldmatrix_x4(ah[1][0], ah[1][1], ah[1][2], ah[1][3], sb + aOff2);
#pragma unroll
            for (int np = 0; np < 4; ++np) {
                uint32_t bo = SWZ((warpN * 64 + np * 16 + bRow) * 128 +
                                  (k16 * 16 + bKoff) * 2);
                ldmatrix_x4(bh[np * 2][0], bh[np * 2][1],
                            bh[np * 2 + 1][0], bh[np * 2 + 1][1], sb + 2 * TILE_B + bo);
            }
            // term 0: Ahi x Bhi
#pragma unroll
            for (int mi = 0; mi < 2; ++mi)
#pragma unroll
                for (int ni = 0; ni < 8; ++ni)
                    mma_bf16(acc[mi][ni], ah[mi], bh[ni]);

            // --- load Blo, term 2: Ahi x Blo
#pragma unroll
            for (int np = 0; np < 4; ++np) {
                uint32_t bo = SWZ((warpN * 64 + np * 16 + bRow) * 128 +
                                  (k16 * 16 + bKoff) * 2);
                ldmatrix_x4(bl[np * 2][0], bl[np * 2][1],
                            bl[np * 2 + 1][0], bl[np * 2 + 1][1], sb + 3 * TILE_B + bo);
            }
#pragma unroll
            for (int mi = 0; mi < 2; ++mi)
#pragma unroll
                for (int ni = 0; ni < 8; ++ni)
                    mma_bf16(acc[mi][ni], ah[mi], bl[ni]);

            // --- load Alo (overwrites ah), term 1: Alo x Bhi
            ldmatrix_x4(ah[0][0], ah[0][1], ah[0][2], ah[0][3], sb + TILE_B + aOff);
            ldmatrix_x4(ah[1][0], ah[1][1], ah[1][2], ah[1][3], sb + TILE_B + aOff2);
#pragma unroll
            for (int mi = 0; mi < 2; ++mi)
#pragma unroll
                for (int ni = 0; ni < 8; ++ni)
                    mma_bf16(acc[mi][ni], ah[mi], bh[ni]);
        }
    }

    // epilogue
#pragma unroll
    for (int mi = 0; mi < 2; ++mi)
#pragma unroll
        for (int ni = 0; ni < 8; ++ni) {
            int row = bm + warpM * 32 + mi * 16 + (lane >> 2);
            int col = bn + warpN * 64 + ni * 8 + (lane & 3) * 2;
#pragma unroll
            for (int hh = 0; hh < 2; ++hh) {
                int r = row + hh * 8;
                float v0 = acc[mi][ni][hh * 2 + 0];
                float v1 = acc[mi][ni][hh * 2 + 1];
                size_t idx = (size_t)r * N + col;
                if (EPI == 2) {
                    v0 = gelu_f(v0); v1 = gelu_f(v1);
                    __nv_bfloat16 h0, h1, l0, l1;
                    split_bf16(v0, h0, l0); split_bf16(v1, h1, l1);
                    __nv_bfloat162 hp(h0, h1), lp(l0, l1);
                    *(uint32_t*)(Chi + idx) = *(uint32_t*)&hp;
                    *(uint32_t*)(Clo + idx) = *(uint32_t*)&lp;
                } else {
                    if (EPI == 1) {
                        float2 rs = *(const float2*)(resid + idx);
                        v0 += bias[col] + rs.x;
                        v1 += bias[col + 1] + rs.y;
                    } else if (EPI == 3) {
                        float2 rs = *(const float2*)(resid + idx);
                        v0 += rs.x; v1 += rs.y;
                    }
                    *(float2*)(Cf + idx) = make_float2(v0, v1);
                }
            }
        }
}

// ------------------------------- launch ---------------------------------------
extern "C" void kernel_launch(void* const* d_in, const int* in_sizes, int n_in,
                              void* d_out, int out_size)
{
    const float* x       = (const float*)d_in[0];
    const float* w_qkv   = (const float*)d_in[1];
    const float* q_scale = (const float*)d_in[2];
    const float* k_scale = (const float*)d_in[3];
    const float* w_out   = (const float*)d_in[4];
    const float* b_out   = (const float*)d_in[5];
    const float* ln1_g   = (const float*)d_in[6];
    const float* ln1_b   = (const float*)d_in[7];
    const float* ff_ln_g = (const float*)d_in[8];
    const float* ff_ln_b = (const float*)d_in[9];
    const float* w_ff1   = (const float*)d_in[10];
    const float* w_ff2   = (const float*)d_in[11];
    float* out = (float*)d_out;

    float *p_qkv, *p_x1;
    __nv_bfloat16 *p_h_hi, *p_h_lo, *p_at_hi, *p_at_lo, *p_f1_hi, *p_f1_lo;
    __nv_bfloat16 *p_wqkv_hi, *p_wqkv_lo, *p_wout_hi, *p_wout_lo;
    __nv_bfloat16 *p_wff1_hi, *p_wff1_lo, *p_wff2_hi, *p_wff2_lo;
    cudaGetSymbolAddress((void**)&p_qkv, g_qkv);
    cudaGetSymbolAddress((void**)&p_x1, g_x1);
    cudaGetSymbolAddress((void**)&p_h_hi, g_h_hi);
    cudaGetSymbolAddress((void**)&p_h_lo, g_h_lo);
    cudaGetSymbolAddress((void**)&p_at_hi, g_at_hi);
    cudaGetSymbolAddress((void**)&p_at_lo, g_at_lo);
    cudaGetSymbolAddress((void**)&p_f1_hi, g_f1_hi);
    cudaGetSymbolAddress((void**)&p_f1_lo, g_f1_lo);
    cudaGetSymbolAddress((void**)&p_wqkv_hi, g_wqkv_hi);
    cudaGetSymbolAddress((void**)&p_wqkv_lo, g_wqkv_lo);
    cudaGetSymbolAddress((void**)&p_wout_hi, g_wout_hi);
    cudaGetSymbolAddress((void**)&p_wout_lo, g_wout_lo);
    cudaGetSymbolAddress((void**)&p_wff1_hi, g_wff1_hi);
    cudaGetSymbolAddress((void**)&p_wff1_lo, g_wff1_lo);
    cudaGetSymbolAddress((void**)&p_wff2_hi, g_wff2_hi);
    cudaGetSymbolAddress((void**)&p_wff2_lo, g_wff2_lo);

    cudaFuncSetAttribute(gemm_tc<0>, cudaFuncAttributeMaxDynamicSharedMemorySize, SM_TOTAL);
    cudaFuncSetAttribute(gemm_tc<1>, cudaFuncAttributeMaxDynamicSharedMemorySize, SM_TOTAL);
    cudaFuncSetAttribute(gemm_tc<2>, cudaFuncAttributeMaxDynamicSharedMemorySize, SM_TOTAL);
    cudaFuncSetAttribute(gemm_tc<3>, cudaFuncAttributeMaxDynamicSharedMemorySize, SM_TOTAL);

    // weight splits
    split_kernel<<<(QKVD * DIMN / 4 + 255) / 256, 256>>>(w_qkv, p_wqkv_hi, p_wqkv_lo, QKVD * DIMN / 4);
    split_kernel<<<(DIMN * DIMN / 4 + 255) / 256, 256>>>(w_out, p_wout_hi, p_wout_lo, DIMN * DIMN / 4);
    split_kernel<<<(FFD * DIMN / 4 + 255) / 256, 256>>>(w_ff1, p_wff1_hi, p_wff1_lo, FFD * DIMN / 4);
    split_kernel<<<(DIMN * FFD / 4 + 255) / 256, 256>>>(w_ff2, p_wff2_hi, p_wff2_lo, DIMN * FFD / 4);

    // 1) h = LN1(x) -> hi/lo
    ln_kernel<<<NTOK, 128>>>(x, ln1_g, ln1_b, p_h_hi, p_h_lo);

    // 2) qkv = h @ w_qkv^T (fp32 out)
    gemm_tc<0><<<dim3(QKVD / 128, NTOK / 128), 256, SM_TOTAL>>>(
        p_h_hi, p_h_lo, p_wqkv_hi, p_wqkv_lo, NTOK, QKVD, DIMN,
        p_qkv, nullptr, nullptr, nullptr, nullptr);

    // 3) l2norm*scale + rotary (in place)
    qkpost_kernel<<<NTOK, 256>>>(p_qkv, q_scale, k_scale);

    // 4) attention -> hi/lo
    attn_kernel<<<dim3(NW, HEADS, BATCH), 128>>>(p_qkv, p_at_hi, p_at_lo);

    // 5) x1 = x + attn @ w_out^T + b_out
    gemm_tc<1><<<dim3(DIMN / 128, NTOK / 128), 256, SM_TOTAL>>>(
        p_at_hi, p_at_lo, p_wout_hi, p_wout_lo, NTOK, DIMN, DIMN,
        p_x1, nullptr, nullptr, b_out, x);

    // 6) h = LN2(x1) -> hi/lo
    ln_kernel<<<NTOK, 128>>>(p_x1, ff_ln_g, ff_ln_b, p_h_hi, p_h_lo);

    // 7) ff1 = gelu(h @ w_ff1^T) -> hi/lo
    gemm_tc<2><<<dim3(FFD / 128, NTOK / 128), 256, SM_TOTAL>>>(
        p_h_hi, p_h_lo, p_wff1_hi, p_wff1_lo, NTOK, FFD, DIMN,
        nullptr, p_f1_hi, p_f1_lo, nullptr, nullptr);

    // 8) out = x1 + ff1 @ w_ff2^T
    gemm_tc<3><<<dim3(DIMN / 128, NTOK / 128), 256, SM_TOTAL>>>(
        p_f1_hi, p_f1_lo, p_wff2_hi, p_wff2_lo, NTOK, DIMN, FFD,
        out, nullptr, nullptr, nullptr, p_x1);
}

// round 9
// speedup vs baseline: 1.3391x; 1.2465x over previous
#include <cuda_runtime.h>
#include <cuda_bf16.h>
#include <cuda_fp16.h>
#include <stdint.h>
#include <math.h>

#define BATCH   8
#define SEQ     4096
#define DIMN    512
#define HEADS   8
#define DHEAD   64
#define WIN     128
#define NW      (SEQ / WIN)
#define NTOK    (BATCH * SEQ)
#define QKVD    (3 * DIMN)
#define FFD     (4 * DIMN)

#define WSCALE     512.0f      // weights pre-scaled by 512 (exact pow2) to keep
#define WSCALE_INV (1.0f / 512.0f)   // fp16 lo-parts out of subnormal range

// ======================= scratch (static device memory) ========================
__device__ float  g_qkv [(size_t)NTOK * QKVD];
__device__ float  g_x1  [(size_t)NTOK * DIMN];
__device__ __half g_h   [(size_t)NTOK * DIMN];   // LN output (single fp16)
__device__ __half g_at  [(size_t)NTOK * DIMN];   // attention output
__device__ __half g_f1  [(size_t)NTOK * FFD];    // gelu(ff1)
__device__ __half g_wqkv_hi[QKVD * DIMN], g_wqkv_lo[QKVD * DIMN];
__device__ __half g_wout_hi[DIMN * DIMN], g_wout_lo[DIMN * DIMN];
__device__ __half g_wff1_hi[FFD * DIMN],  g_wff1_lo[FFD * DIMN];
__device__ __half g_wff2_hi[DIMN * FFD],  g_wff2_lo[DIMN * FFD];

// ============================ helpers ==========================================
__device__ __forceinline__ uint32_t smem_u32(const void* p) {
    uint32_t a;
    asm("{ .reg .u64 t; cvta.to.shared.u64 t, %1; cvt.u32.u64 %0, t; }" : "=r"(a) : "l"(p));
    return a;
}
#define SWZ(o) ((o) ^ (((o) >> 3) & 0x70))   // SW128 swizzle, 128B rows

__device__ __forceinline__ void cp_async16(uint32_t dst, const void* src) {
    asm volatile("cp.async.cg.shared.global [%0], [%1], 16;" :: "r"(dst), "l"(src));
}
__device__ __forceinline__ void cp_commit_wait() {
    asm volatile("cp.async.commit_group;");
    asm volatile("cp.async.wait_group 0;");
}
__device__ __forceinline__ void ldmatrix_x4(uint32_t& r0, uint32_t& r1,
                                            uint32_t& r2, uint32_t& r3, uint32_t a) {
    asm volatile("ldmatrix.sync.aligned.m8n8.x4.shared.b16 {%0,%1,%2,%3}, [%4];"
                 : "=r"(r0), "=r"(r1), "=r"(r2), "=r"(r3) : "r"(a));
}
__device__ __forceinline__ void mma_fp16(float* c, const uint32_t* a, const uint32_t* b) {
    asm volatile("mma.sync.aligned.m16n8k16.row.col.f32.f16.f16.f32 "
                 "{%0,%1,%2,%3}, {%4,%5,%6,%7}, {%8,%9}, {%0,%1,%2,%3};"
                 : "+f"(c[0]), "+f"(c[1]), "+f"(c[2]), "+f"(c[3])
                 : "r"(a[0]), "r"(a[1]), "r"(a[2]), "r"(a[3]), "r"(b[0]), "r"(b[1]));
}

// ================= LayerNorm -> single fp16. block = token =====================
__global__ __launch_bounds__(128) void ln_kernel(const float* __restrict__ in,
                                                 const float* __restrict__ gamma,
                                                 const float* __restrict__ beta,
                                                 __half* __restrict__ oh)
{
    int t = blockIdx.x;
    int tid = threadIdx.x;
    const float4* row = (const float4*)(in + (size_t)t * DIMN);
    float4 v = row[tid];
    float s  = v.x + v.y + v.z + v.w;
    float ss = v.x * v.x + v.y * v.y + v.z * v.z + v.w * v.w;
#pragma unroll
    for (int o = 16; o > 0; o >>= 1) {
        s  += __shfl_xor_sync(0xffffffffu, s, o);
        ss += __shfl_xor_sync(0xffffffffu, ss, o);
    }
    __shared__ float sm[4], sm2[4];
    int w = tid >> 5, lane = tid & 31;
    if (lane == 0) { sm[w] = s; sm2[w] = ss; }
    __syncthreads();
    s  = sm[0] + sm[1] + sm[2] + sm[3];
    ss = sm2[0] + sm2[1] + sm2[2] + sm2[3];
    float mean = s * (1.0f / DIMN);
    float var  = ss * (1.0f / DIMN) - mean * mean;
    float inv  = rsqrtf(var + 1e-5f);
    float4 g = ((const float4*)gamma)[tid];
    float4 b = ((const float4*)beta)[tid];
    float o0 = (v.x - mean) * inv * g.x + b.x;
    float o1 = (v.y - mean) * inv * g.y + b.y;
    float o2 = (v.z - mean) * inv * g.z + b.z;
    float o3 = (v.w - mean) * inv * g.w + b.w;
    __half2 p0 = __floats2half2_rn(o0, o1);
    __half2 p1 = __floats2half2_rn(o2, o3);
    *(uint2*)(oh + (size_t)t * DIMN + tid * 4) = make_uint2(*(uint32_t*)&p0, *(uint32_t*)&p1);
}

// ========= weight split: fp32 -> fp16 hi/lo of (512 * w) ========================
__global__ void split_kernel(const float* __restrict__ in,
                             __half* __restrict__ hi,
                             __half* __restrict__ lo, int n4)
{
    int i = blockIdx.x * blockDim.x + threadIdx.x;
    if (i >= n4) return;
    float4 v = ((const float4*)in)[i];
    float s0 = v.x * WSCALE, s1 = v.y * WSCALE, s2 = v.z * WSCALE, s3 = v.w * WSCALE;
    __half h0 = __float2half_rn(s0), h1 = __float2half_rn(s1);
    __half h2 = __float2half_rn(s2), h3 = __float2half_rn(s3);
    __half l0 = __float2half_rn(s0 - __half2float(h0));
    __half l1 = __float2half_rn(s1 - __half2float(h1));
    __half l2 = __float2half_rn(s2 - __half2float(h2));
    __half l3 = __float2half_rn(s3 - __half2float(h3));
    __half2 ph0(h0, h1), ph1(h2, h3), pl0(l0, l1), pl1(l2, l3);
    ((uint2*)hi)[i] = make_uint2(*(uint32_t*)&ph0, *(uint32_t*)&ph1);
    ((uint2*)lo)[i] = make_uint2(*(uint32_t*)&pl0, *(uint32_t*)&pl1);
}

// ========= q/k post: l2norm*scale + rotary (double trig, fp32 phase) ============
__global__ __launch_bounds__(256) void qkpost_kernel(float* __restrict__ qkv,
                                                     const float* __restrict__ qsc,
                                                     const float* __restrict__ ksc)
{
    int t = blockIdx.x;
    int n = t & (SEQ - 1);
    int h = threadIdx.x >> 5;
    int lane = threadIdx.x & 31;

    double invf_d = exp(-(double)(2 * lane) * (9.210340371976184 / 64.0));
    float invf = (float)invf_d;
    float ph = (float)n * invf;
    double sd, cd;
    sincos((double)ph, &sd, &cd);
    float c = (float)cd, s = (float)sd;

    float* base = qkv + (size_t)t * QKVD + h * DHEAD;
    {
        float a = base[lane], b = base[lane + 32];
        float ssq = a * a + b * b;
#pragma unroll
        for (int o = 16; o > 0; o >>= 1) ssq += __shfl_xor_sync(0xffffffffu, ssq, o);
        float inv = 1.0f / fmaxf(sqrtf(ssq), 1e-12f);
        float an = a * inv * qsc[lane];
        float bn = b * inv * qsc[lane + 32];
        base[lane]      = an * c - bn * s;
        base[lane + 32] = bn * c + an * s;
    }
    {
        float* kb = base + DIMN;
        float a = kb[lane], b = kb[lane + 32];
        float ssq = a * a + b * b;
#pragma unroll
        for (int o = 16; o > 0; o >>= 1) ssq += __shfl_xor_sync(0xffffffffu, ssq, o);
        float inv = 1.0f / fmaxf(sqrtf(ssq), 1e-12f);
        float an = a * inv * ksc[lane];
        float bn = b * inv * ksc[lane + 32];
        kb[lane]      = an * c - bn * s;
        kb[lane + 32] = bn * c + an * s;
    }
}

// ====== local-window attention: fixed-offset softmax (scores bounded) ==========
// q,k l2-normalized => |score| <= 8*|qsc|*|ksc|; exp(sc) cannot overflow fp32
// (needs ~88). softmax(sc) = exp(sc)/sum exp(sc) exactly, so no running max and
// no accumulator rescaling: 1 FMA per dim per key instead of 2.
__global__ __launch_bounds__(128) void attn_kernel(const float* __restrict__ qkv,
                                                   __half* __restrict__ oh)
{
    __shared__ float sK[64][DHEAD];
    __shared__ float sV[64][DHEAD];

    int w = blockIdx.x, h = blockIdx.y, b = blockIdx.z;
    int i = threadIdx.x;
    int tok0 = b * SEQ + w * WIN;
    int tok  = tok0 + i;

    float q[DHEAD];
    {
        const float4* srcQ = (const float4*)(qkv + (size_t)tok * QKVD + h * DHEAD);
#pragma unroll
        for (int d4 = 0; d4 < 16; ++d4) {
            float4 t4 = srcQ[d4];
            q[d4 * 4 + 0] = t4.x; q[d4 * 4 + 1] = t4.y;
            q[d4 * 4 + 2] = t4.z; q[d4 * 4 + 3] = t4.w;
        }
    }

    float acc[DHEAD];
#pragma unroll
    for (int d = 0; d < DHEAD; ++d) acc[d] = 0.f;
    float l = 0.f;

#pragma unroll 1
    for (int c = 0; c < 4; ++c) {
        if (c < 2 && w == 0) continue;

        __syncthreads();
        {
            int r  = i >> 1;
            int f0 = (i & 1) * 8;
            int ktok = tok0 + c * 64 - WIN + r;
            const float4* sk = (const float4*)(qkv + (size_t)ktok * QKVD + DIMN + h * DHEAD);
            const float4* sv = (const float4*)(qkv + (size_t)ktok * QKVD + 2 * DIMN + h * DHEAD);
            float4* dK = (float4*)&sK[r][0];
            float4* dV = (float4*)&sV[r][0];
#pragma unroll
            for (int f = 0; f < 8; ++f) { dK[f0 + f] = sk[f0 + f]; dV[f0 + f] = sv[f0 + f]; }
        }
        __syncthreads();

        int jmax;
        if (c < 2) jmax = 64;
        else {
            jmax = i - (c - 2) * 64 + 1;
            jmax = jmax < 0 ? 0 : (jmax > 64 ? 64 : jmax);
        }
        for (int j = 0; j < jmax; ++j) {
            const float4* kr = (const float4*)&sK[j][0];
            float s0 = 0.f, s1 = 0.f, s2 = 0.f, s3 = 0.f;
#pragma unroll
            for (int d4 = 0; d4 < 16; ++d4) {
                float4 kv = kr[d4];
                s0 += q[d4 * 4 + 0] * kv.x;
                s1 += q[d4 * 4 + 1] * kv.y;
                s2 += q[d4 * 4 + 2] * kv.z;
                s3 += q[d4 * 4 + 3] * kv.w;
            }
            float sc = ((s0 + s1) + (s2 + s3)) * 8.0f;   // QK_SCALE
            float p  = __expf(sc);                        // |sc|<=8: no overflow
            l += p;
            const float4* vr = (const float4*)&sV[j][0];
#pragma unroll
            for (int d4 = 0; d4 < 16; ++d4) {
                float4 vv = vr[d4];
                acc[d4 * 4 + 0] += p * vv.x;
                acc[d4 * 4 + 1] += p * vv.y;
                acc[d4 * 4 + 2] += p * vv.z;
                acc[d4 * 4 + 3] += p * vv.w;
            }
        }
    }

    float invl = 1.0f / l;
    size_t dstoff = (size_t)tok * DIMN + h * DHEAD;
#pragma unroll
    for (int d4 = 0; d4 < 16; ++d4) {
        __half2 p0 = __floats2half2_rn(acc[d4 * 4 + 0] * invl, acc[d4 * 4 + 1] * invl);
        __half2 p1 = __floats2half2_rn(acc[d4 * 4 + 2] * invl, acc[d4 * 4 + 3] * invl);
        *(uint2*)(oh + dstoff + d4 * 4) = make_uint2(*(uint32_t*)&p0, *(uint32_t*)&p1);
    }
}

// ====== HMMA GEMM, fp16 2-term (A single, B split): C = A*Bhi + A*Blo ==========
// B pre-scaled by 512 -> acc scaled back by 1/512 in epilogue.
// 256 threads = 8 warps: warpM = wid&3 (32 rows), warpN = wid>>2 (64 cols).
// smem: 3 tiles (A, Bhi, Blo) of 128x64 fp16 (SW128); 48KB -> 2 CTAs/SM.
// EPI: 0 fp32 | 1 +bias+resid fp32 | 2 gelu -> fp16 | 3 +resid fp32
#define KBLK     64
#define TILE_B   16384
#define SM_TOTAL (3 * TILE_B)

__device__ __forceinline__ float gelu_f(float x)
{
    return 0.5f * x * (1.0f + erff(x * 0.7071067811865476f));
}

template <int EPI>
__global__ __launch_bounds__(256, 2) void gemm_tc(
    const __half* __restrict__ A,
    const __half* __restrict__ Bhi, const __half* __restrict__ Blo,
    int M, int N, int K,
    float* __restrict__ Cf, __half* __restrict__ Ch,
    const float* __restrict__ bias, const float* __restrict__ resid)
{
    extern __shared__ char smem[];
    uint32_t sb = smem_u32(smem);
    int tid = threadIdx.x, wid = tid >> 5, lane = tid & 31;
    int warpM = wid & 3, warpN = wid >> 2;
    int bm = blockIdx.y * 128, bn = blockIdx.x * 128;

    float acc[2][8][4];
#pragma unroll
    for (int mi = 0; mi < 2; ++mi)
#pragma unroll
        for (int ni = 0; ni < 8; ++ni)
#pragma unroll
            for (int r = 0; r < 4; ++r) acc[mi][ni][r] = 0.f;

    // ldmatrix lane->address mapping
    int aRow  = lane & 15;
    int aKoff = (lane >> 4) << 3;
    int bRow  = (lane & 7) + ((lane >> 4) << 3);
    int bKoff = ((lane >> 3) & 1) << 3;

    int kchunks = K / KBLK;
#pragma unroll 1
    for (int kc = 0; kc < kchunks; ++kc) {
        int k0 = kc * KBLK;
        __syncthreads();
        // fill 3 tiles via cp.async (each thread: 12 x 16B)
#pragma unroll
        for (int tile = 0; tile < 3; ++tile) {
            const __half* src = (tile == 0) ? A : (tile == 1) ? Bhi : Blo;
            int rbase = (tile == 0) ? bm : bn;
            uint32_t dstb = sb + tile * TILE_B;
#pragma unroll
            for (int it = 0; it < 4; ++it) {
                int idx = tid + it * 256;
                int row = idx >> 3, c16 = idx & 7;
                cp_async16(dstb + SWZ(row * 128 + c16 * 16),
                           src + (size_t)(rbase + row) * K + k0 + c16 * 8);
            }
        }
        cp_commit_wait();
        __syncthreads();

#pragma unroll 1
        for (int k16 = 0; k16 < KBLK / 16; ++k16) {
            uint32_t aOff  = SWZ((warpM * 32 + aRow) * 128 + (k16 * 16 + aKoff) * 2);
            uint32_t aOff2 = SWZ((warpM * 32 + 16 + aRow) * 128 + (k16 * 16 + aKoff) * 2);
            uint32_t a[2][4], bh[8][2], bl[8][2];

            // A fragments (loaded once, reused for both terms)
            ldmatrix_x4(a[0][0], a[0][1], a[0][2], a[0][3], sb + aOff);
            ldmatrix_x4(a[1][0], a[1][1], a[1][2], a[1][3], sb + aOff2);
            // Bhi fragments + term 0
#pragma unroll
            for (int np = 0; np < 4; ++np) {
                uint32_t bo = SWZ((warpN * 64 + np * 16 + bRow) * 128 +
                                  (k16 * 16 + bKoff) * 2);
                ldmatrix_x4(bh[np * 2][0], bh[np * 2][1],
                            bh[np * 2 + 1][0], bh[np * 2 + 1][1], sb + TILE_B + bo);
            }
#pragma unroll
            for (int mi = 0; mi < 2; ++mi)
#pragma unroll
                for (int ni = 0; ni < 8; ++ni)
                    mma_fp16(acc[mi][ni], a[mi], bh[ni]);
            // Blo fragments + term 1
#pragma unroll
            for (int np = 0; np < 4; ++np) {
                uint32_t bo = SWZ((warpN * 64 + np * 16 + bRow) * 128 +
                                  (k16 * 16 + bKoff) * 2);
                ldmatrix_x4(bl[np * 2][0], bl[np * 2][1],
                            bl[np * 2 + 1][0], bl[np * 2 + 1][1], sb + 2 * TILE_B + bo);
            }
#pragma unroll
            for (int mi = 0; mi < 2; ++mi)
#pragma unroll
                for (int ni = 0; ni < 8; ++ni)
                    mma_fp16(acc[mi][ni], a[mi], bl[ni]);
        }
    }

    // epilogue (undo WSCALE)
#pragma unroll
    for (int mi = 0; mi < 2; ++mi)
#pragma unroll
        for (int ni = 0; ni < 8; ++ni) {
            int row = bm + warpM * 32 + mi * 16 + (lane >> 2);
            int col = bn + warpN * 64 + ni * 8 + (lane & 3) * 2;
#pragma unroll
            for (int hh = 0; hh < 2; ++hh) {
                int r = row + hh * 8;
                float v0 = acc[mi][ni][hh * 2 + 0] * WSCALE_INV;
                float v1 = acc[mi][ni][hh * 2 + 1] * WSCALE_INV;
                size_t idx = (size_t)r * N + col;
                if (EPI == 2) {
                    __half2 hp = __floats2half2_rn(gelu_f(v0), gelu_f(v1));
                    *(uint32_t*)(Ch + idx) = *(uint32_t*)&hp;
                } else {
                    if (EPI == 1) {
                        float2 rs = *(const float2*)(resid + idx);
                        v0 += bias[col] + rs.x;
                        v1 += bias[col + 1] + rs.y;
                    } else if (EPI == 3) {
                        float2 rs = *(const float2*)(resid + idx);
                        v0 += rs.x; v1 += rs.y;
                    }
                    *(float2*)(Cf + idx) = make_float2(v0, v1);
                }
            }
        }
}

// ------------------------------- launch ---------------------------------------
extern "C" void kernel_launch(void* const* d_in, const int* in_sizes, int n_in,
                              void* d_out, int out_size)
{
    const float* x       = (const float*)d_in[0];
    const float* w_qkv   = (const float*)d_in[1];
    const float* q_scale = (const float*)d_in[2];
    const float* k_scale = (const float*)d_in[3];
    const float* w_out   = (const float*)d_in[4];
    const float* b_out   = (const float*)d_in[5];
    const float* ln1_g   = (const float*)d_in[6];
    const float* ln1_b   = (const float*)d_in[7];
    const float* ff_ln_g = (const float*)d_in[8];
    const float* ff_ln_b = (const float*)d_in[9];
    const float* w_ff1   = (const float*)d_in[10];
    const float* w_ff2   = (const float*)d_in[11];
    float* out = (float*)d_out;

    float *p_qkv, *p_x1;
    __half *p_h, *p_at, *p_f1;
    __half *p_wqkv_hi, *p_wqkv_lo, *p_wout_hi, *p_wout_lo;
    __half *p_wff1_hi, *p_wff1_lo, *p_wff2_hi, *p_wff2_lo;
    cudaGetSymbolAddress((void**)&p_qkv, g_qkv);
    cudaGetSymbolAddress((void**)&p_x1, g_x1);
    cudaGetSymbolAddress((void**)&p_h, g_h);
    cudaGetSymbolAddress((void**)&p_at, g_at);
    cudaGetSymbolAddress((void**)&p_f1, g_f1);
    cudaGetSymbolAddress((void**)&p_wqkv_hi, g_wqkv_hi);
    cudaGetSymbolAddress((void**)&p_wqkv_lo, g_wqkv_lo);
    cudaGetSymbolAddress((void**)&p_wout_hi, g_wout_hi);
    cudaGetSymbolAddress((void**)&p_wout_lo, g_wout_lo);
    cudaGetSymbolAddress((void**)&p_wff1_hi, g_wff1_hi);
    cudaGetSymbolAddress((void**)&p_wff1_lo, g_wff1_lo);
    cudaGetSymbolAddress((void**)&p_wff2_hi, g_wff2_hi);
    cudaGetSymbolAddress((void**)&p_wff2_lo, g_wff2_lo);

    cudaFuncSetAttribute(gemm_tc<0>, cudaFuncAttributeMaxDynamicSharedMemorySize, SM_TOTAL);
    cudaFuncSetAttribute(gemm_tc<1>, cudaFuncAttributeMaxDynamicSharedMemorySize, SM_TOTAL);
    cudaFuncSetAttribute(gemm_tc<2>, cudaFuncAttributeMaxDynamicSharedMemorySize, SM_TOTAL);
    cudaFuncSetAttribute(gemm_tc<3>, cudaFuncAttributeMaxDynamicSharedMemorySize, SM_TOTAL);

    // weight splits (fp16 hi/lo of 512*w)
    split_kernel<<<(QKVD * DIMN / 4 + 255) / 256, 256>>>(w_qkv, p_wqkv_hi, p_wqkv_lo, QKVD * DIMN / 4);
    split_kernel<<<(DIMN * DIMN / 4 + 255) / 256, 256>>>(w_out, p_wout_hi, p_wout_lo, DIMN * DIMN / 4);
    split_kernel<<<(FFD * DIMN / 4 + 255) / 256, 256>>>(w_ff1, p_wff1_hi, p_wff1_lo, FFD * DIMN / 4);
    split_kernel<<<(DIMN * FFD / 4 + 255) / 256, 256>>>(w_ff2, p_wff2_hi, p_wff2_lo, DIMN * FFD / 4);

    // 1) h = LN1(x) -> fp16
    ln_kernel<<<NTOK, 128>>>(x, ln1_g, ln1_b, p_h);

    // 2) qkv = h @ w_qkv^T (fp32 out)
    gemm_tc<0><<<dim3(QKVD / 128, NTOK / 128), 256, SM_TOTAL>>>(
        p_h, p_wqkv_hi, p_wqkv_lo, NTOK, QKVD, DIMN,
        p_qkv, nullptr, nullptr, nullptr);

    // 3) l2norm*scale + rotary (in place)
    qkpost_kernel<<<NTOK, 256>>>(p_qkv, q_scale, k_scale);

    // 4) attention -> fp16
    attn_kernel<<<dim3(NW, HEADS, BATCH), 128>>>(p_qkv, p_at);

    // 5) x1 = x + attn @ w_out^T + b_out
    gemm_tc<1><<<dim3(DIMN / 128, NTOK / 128), 256, SM_TOTAL>>>(
        p_at, p_wout_hi, p_wout_lo, NTOK, DIMN, DIMN,
        p_x1, nullptr, b_out, x);

    // 6) h = LN2(x1) -> fp16
    ln_kernel<<<NTOK, 128>>>(p_x1, ff_ln_g, ff_ln_b, p_h);

    // 7) ff1 = gelu(h @ w_ff1^T) -> fp16
    gemm_tc<2><<<dim3(FFD / 128, NTOK / 128), 256, SM_TOTAL>>>(
        p_h, p_wff1_hi, p_wff1_lo, NTOK, FFD, DIMN,
        nullptr, p_f1, nullptr, nullptr);

    // 8) out = x1 + ff1 @ w_ff2^T
    gemm_tc<3><<<dim3(DIMN / 128, NTOK / 128), 256, SM_TOTAL>>>(
        p_f1, p_wff2_hi, p_wff2_lo, NTOK, DIMN, FFD,
        out, nullptr, nullptr, p_x1);
}

// round 10
// speedup vs baseline: 1.5824x; 1.1818x over previous
#include <cuda_runtime.h>
#include <cuda_bf16.h>
#include <cuda_fp16.h>
#include <stdint.h>
#include <math.h>

#define BATCH   8
#define SEQ     4096
#define DIMN    512
#define HEADS   8
#define DHEAD   64
#define WIN     128
#define NW      (SEQ / WIN)
#define NTOK    (BATCH * SEQ)
#define QKVD    (3 * DIMN)
#define FFD     (4 * DIMN)

#define WSCALE     512.0f            // weights pre-scaled by 512 (exact pow2)
#define WSCALE_INV (1.0f / 512.0f)   // keeps fp16 weights well inside normal range

// ======================= scratch (static device memory) ========================
__device__ float  g_qkv [(size_t)NTOK * QKVD];
__device__ float  g_x1  [(size_t)NTOK * DIMN];
__device__ __half g_h   [(size_t)NTOK * DIMN];   // LN output (fp16)
__device__ __half g_at  [(size_t)NTOK * DIMN];   // attention output
__device__ __half g_f1  [(size_t)NTOK * FFD];    // gelu(ff1)
__device__ __half g_wqkv[QKVD * DIMN];
__device__ __half g_wout[DIMN * DIMN];
__device__ __half g_wff1[FFD * DIMN];
__device__ __half g_wff2[DIMN * FFD];

// ============================ helpers ==========================================
__device__ __forceinline__ uint32_t smem_u32(const void* p) {
    uint32_t a;
    asm("{ .reg .u64 t; cvta.to.shared.u64 t, %1; cvt.u32.u64 %0, t; }" : "=r"(a) : "l"(p));
    return a;
}
#define SWZ(o) ((o) ^ (((o) >> 3) & 0x70))   // SW128 swizzle, 128B rows

__device__ __forceinline__ void cp_async16(uint32_t dst, const void* src) {
    asm volatile("cp.async.cg.shared.global [%0], [%1], 16;" :: "r"(dst), "l"(src));
}
__device__ __forceinline__ void cp_commit_wait() {
    asm volatile("cp.async.commit_group;");
    asm volatile("cp.async.wait_group 0;");
}
__device__ __forceinline__ void ldmatrix_x4(uint32_t& r0, uint32_t& r1,
                                            uint32_t& r2, uint32_t& r3, uint32_t a) {
    asm volatile("ldmatrix.sync.aligned.m8n8.x4.shared.b16 {%0,%1,%2,%3}, [%4];"
                 : "=r"(r0), "=r"(r1), "=r"(r2), "=r"(r3) : "r"(a));
}
__device__ __forceinline__ void mma_fp16(float* c, const uint32_t* a, const uint32_t* b) {
    asm volatile("mma.sync.aligned.m16n8k16.row.col.f32.f16.f16.f32 "
                 "{%0,%1,%2,%3}, {%4,%5,%6,%7}, {%8,%9}, {%0,%1,%2,%3};"
                 : "+f"(c[0]), "+f"(c[1]), "+f"(c[2]), "+f"(c[3])
                 : "r"(a[0]), "r"(a[1]), "r"(a[2]), "r"(a[3]), "r"(b[0]), "r"(b[1]));
}

// ================= LayerNorm -> fp16. block = token =============================
__global__ __launch_bounds__(128) void ln_kernel(const float* __restrict__ in,
                                                 const float* __restrict__ gamma,
                                                 const float* __restrict__ beta,
                                                 __half* __restrict__ oh)
{
    int t = blockIdx.x;
    int tid = threadIdx.x;
    const float4* row = (const float4*)(in + (size_t)t * DIMN);
    float4 v = row[tid];
    float s  = v.x + v.y + v.z + v.w;
    float ss = v.x * v.x + v.y * v.y + v.z * v.z + v.w * v.w;
#pragma unroll
    for (int o = 16; o > 0; o >>= 1) {
        s  += __shfl_xor_sync(0xffffffffu, s, o);
        ss += __shfl_xor_sync(0xffffffffu, ss, o);
    }
    __shared__ float sm[4], sm2[4];
    int w = tid >> 5, lane = tid & 31;
    if (lane == 0) { sm[w] = s; sm2[w] = ss; }
    __syncthreads();
    s  = sm[0] + sm[1] + sm[2] + sm[3];
    ss = sm2[0] + sm2[1] + sm2[2] + sm2[3];
    float mean = s * (1.0f / DIMN);
    float var  = ss * (1.0f / DIMN) - mean * mean;
    float inv  = rsqrtf(var + 1e-5f);
    float4 g = ((const float4*)gamma)[tid];
    float4 b = ((const float4*)beta)[tid];
    float o0 = (v.x - mean) * inv * g.x + b.x;
    float o1 = (v.y - mean) * inv * g.y + b.y;
    float o2 = (v.z - mean) * inv * g.z + b.z;
    float o3 = (v.w - mean) * inv * g.w + b.w;
    __half2 p0 = __floats2half2_rn(o0, o1);
    __half2 p1 = __floats2half2_rn(o2, o3);
    *(uint2*)(oh + (size_t)t * DIMN + tid * 4) = make_uint2(*(uint32_t*)&p0, *(uint32_t*)&p1);
}

// ========= weight convert: fp32 -> fp16 of (512 * w) ============================
__global__ void wconv_kernel(const float* __restrict__ in,
                             __half* __restrict__ oh, int n4)
{
    int i = blockIdx.x * blockDim.x + threadIdx.x;
    if (i >= n4) return;
    float4 v = ((const float4*)in)[i];
    __half2 p0 = __floats2half2_rn(v.x * WSCALE, v.y * WSCALE);
    __half2 p1 = __floats2half2_rn(v.z * WSCALE, v.w * WSCALE);
    ((uint2*)oh)[i] = make_uint2(*(uint32_t*)&p0, *(uint32_t*)&p1);
}

// ========= q/k post: l2norm*scale + rotary (double trig, fp32 phase) ============
__global__ __launch_bounds__(256) void qkpost_kernel(float* __restrict__ qkv,
                                                     const float* __restrict__ qsc,
                                                     const float* __restrict__ ksc)
{
    int t = blockIdx.x;
    int n = t & (SEQ - 1);
    int h = threadIdx.x >> 5;
    int lane = threadIdx.x & 31;

    double invf_d = exp(-(double)(2 * lane) * (9.210340371976184 / 64.0));
    float invf = (float)invf_d;
    float ph = (float)n * invf;
    double sd, cd;
    sincos((double)ph, &sd, &cd);
    float c = (float)cd, s = (float)sd;

    float* base = qkv + (size_t)t * QKVD + h * DHEAD;
    {
        float a = base[lane], b = base[lane + 32];
        float ssq = a * a + b * b;
#pragma unroll
        for (int o = 16; o > 0; o >>= 1) ssq += __shfl_xor_sync(0xffffffffu, ssq, o);
        float inv = 1.0f / fmaxf(sqrtf(ssq), 1e-12f);
        float an = a * inv * qsc[lane];
        float bn = b * inv * qsc[lane + 32];
        base[lane]      = an * c - bn * s;
        base[lane + 32] = bn * c + an * s;
    }
    {
        float* kb = base + DIMN;
        float a = kb[lane], b = kb[lane + 32];
        float ssq = a * a + b * b;
#pragma unroll
        for (int o = 16; o > 0; o >>= 1) ssq += __shfl_xor_sync(0xffffffffu, ssq, o);
        float inv = 1.0f / fmaxf(sqrtf(ssq), 1e-12f);
        float an = a * inv * ksc[lane];
        float bn = b * inv * ksc[lane + 32];
        kb[lane]      = an * c - bn * s;
        kb[lane + 32] = bn * c + an * s;
    }
}

// ====== local-window attention: fixed-offset softmax (scores bounded) ==========
__global__ __launch_bounds__(128) void attn_kernel(const float* __restrict__ qkv,
                                                   __half* __restrict__ oh)
{
    __shared__ float sK[64][DHEAD];
    __shared__ float sV[64][DHEAD];

    int w = blockIdx.x, h = blockIdx.y, b = blockIdx.z;
    int i = threadIdx.x;
    int tok0 = b * SEQ + w * WIN;
    int tok  = tok0 + i;

    float q[DHEAD];
    {
        const float4* srcQ = (const float4*)(qkv + (size_t)tok * QKVD + h * DHEAD);
#pragma unroll
        for (int d4 = 0; d4 < 16; ++d4) {
            float4 t4 = srcQ[d4];
            q[d4 * 4 + 0] = t4.x; q[d4 * 4 + 1] = t4.y;
            q[d4 * 4 + 2] = t4.z; q[d4 * 4 + 3] = t4.w;
        }
    }

    float acc[DHEAD];
#pragma unroll
    for (int d = 0; d < DHEAD; ++d) acc[d] = 0.f;
    float l = 0.f;

#pragma unroll 1
    for (int c = 0; c < 4; ++c) {
        if (c < 2 && w == 0) continue;

        __syncthreads();
        {
            int r  = i >> 1;
            int f0 = (i & 1) * 8;
            int ktok = tok0 + c * 64 - WIN + r;
            const float4* sk = (const float4*)(qkv + (size_t)ktok * QKVD + DIMN + h * DHEAD);
            const float4* sv = (const float4*)(qkv + (size_t)ktok * QKVD + 2 * DIMN + h * DHEAD);
            float4* dK = (float4*)&sK[r][0];
            float4* dV = (float4*)&sV[r][0];
#pragma unroll
            for (int f = 0; f < 8; ++f) { dK[f0 + f] = sk[f0 + f]; dV[f0 + f] = sv[f0 + f]; }
        }
        __syncthreads();

        int jmax;
        if (c < 2) jmax = 64;
        else {
            jmax = i - (c - 2) * 64 + 1;
            jmax = jmax < 0 ? 0 : (jmax > 64 ? 64 : jmax);
        }
        for (int j = 0; j < jmax; ++j) {
            const float4* kr = (const float4*)&sK[j][0];
            float s0 = 0.f, s1 = 0.f, s2 = 0.f, s3 = 0.f;
#pragma unroll
            for (int d4 = 0; d4 < 16; ++d4) {
                float4 kv = kr[d4];
                s0 += q[d4 * 4 + 0] * kv.x;
                s1 += q[d4 * 4 + 1] * kv.y;
                s2 += q[d4 * 4 + 2] * kv.z;
                s3 += q[d4 * 4 + 3] * kv.w;
            }
            float sc = ((s0 + s1) + (s2 + s3)) * 8.0f;   // QK_SCALE
            float p  = __expf(sc);                        // |sc|<=8: no overflow
            l += p;
            const float4* vr = (const float4*)&sV[j][0];
#pragma unroll
            for (int d4 = 0; d4 < 16; ++d4) {
                float4 vv = vr[d4];
                acc[d4 * 4 + 0] += p * vv.x;
                acc[d4 * 4 + 1] += p * vv.y;
                acc[d4 * 4 + 2] += p * vv.z;
                acc[d4 * 4 + 3] += p * vv.w;
            }
        }
    }

    float invl = 1.0f / l;
    size_t dstoff = (size_t)tok * DIMN + h * DHEAD;
#pragma unroll
    for (int d4 = 0; d4 < 16; ++d4) {
        __half2 p0 = __floats2half2_rn(acc[d4 * 4 + 0] * invl, acc[d4 * 4 + 1] * invl);
        __half2 p1 = __floats2half2_rn(acc[d4 * 4 + 2] * invl, acc[d4 * 4 + 3] * invl);
        *(uint2*)(oh + dstoff + d4 * 4) = make_uint2(*(uint32_t*)&p0, *(uint32_t*)&p1);
    }
}

// ====== HMMA GEMM, plain fp16: C = (A @ (512*B)^T) / 512 =======================
// 256 threads = 8 warps: warpM = wid&3 (32 rows), warpN = wid>>2 (64 cols).
// smem: 2 tiles (A, B) of 128x64 fp16 (SW128); 32KB -> 2 CTAs/SM (reg-bound).
// EPI: 0 fp32 | 1 +bias+resid fp32 | 2 gelu -> fp16 | 3 +resid fp32
#define KBLK     64
#define TILE_B   16384
#define SM_TOTAL (2 * TILE_B)

__device__ __forceinline__ float gelu_f(float x)
{
    return 0.5f * x * (1.0f + erff(x * 0.7071067811865476f));
}

template <int EPI>
__global__ __launch_bounds__(256, 2) void gemm_tc(
    const __half* __restrict__ A, const __half* __restrict__ B,
    int M, int N, int K,
    float* __restrict__ Cf, __half* __restrict__ Ch,
    const float* __restrict__ bias, const float* __restrict__ resid)
{
    extern __shared__ char smem[];
    uint32_t sb = smem_u32(smem);
    int tid = threadIdx.x, wid = tid >> 5, lane = tid & 31;
    int warpM = wid & 3, warpN = wid >> 2;
    int bm = blockIdx.y * 128, bn = blockIdx.x * 128;

    float acc[2][8][4];
#pragma unroll
    for (int mi = 0; mi < 2; ++mi)
#pragma unroll
        for (int ni = 0; ni < 8; ++ni)
#pragma unroll
            for (int r = 0; r < 4; ++r) acc[mi][ni][r] = 0.f;

    // ldmatrix lane->address mapping
    int aRow  = lane & 15;
    int aKoff = (lane >> 4) << 3;
    int bRow  = (lane & 7) + ((lane >> 4) << 3);
    int bKoff = ((lane >> 3) & 1) << 3;

    int kchunks = K / KBLK;
#pragma unroll 1
    for (int kc = 0; kc < kchunks; ++kc) {
        int k0 = kc * KBLK;
        __syncthreads();
        // fill 2 tiles via cp.async (each thread: 8 x 16B)
#pragma unroll
        for (int tile = 0; tile < 2; ++tile) {
            const __half* src = (tile == 0) ? A : B;
            int rbase = (tile == 0) ? bm : bn;
            uint32_t dstb = sb + tile * TILE_B;
#pragma unroll
            for (int it = 0; it < 4; ++it) {
                int idx = tid + it * 256;
                int row = idx >> 3, c16 = idx & 7;
                cp_async16(dstb + SWZ(row * 128 + c16 * 16),
                           src + (size_t)(rbase + row) * K + k0 + c16 * 8);
            }
        }
        cp_commit_wait();
        __syncthreads();

#pragma unroll
        for (int k16 = 0; k16 < KBLK / 16; ++k16) {
            uint32_t aOff  = SWZ((warpM * 32 + aRow) * 128 + (k16 * 16 + aKoff) * 2);
            uint32_t aOff2 = SWZ((warpM * 32 + 16 + aRow) * 128 + (k16 * 16 + aKoff) * 2);
            uint32_t a[2][4], b[8][2];

            ldmatrix_x4(a[0][0], a[0][1], a[0][2], a[0][3], sb + aOff);
            ldmatrix_x4(a[1][0], a[1][1], a[1][2], a[1][3], sb + aOff2);
#pragma unroll
            for (int np = 0; np < 4; ++np) {
                uint32_t bo = SWZ((warpN * 64 + np * 16 + bRow) * 128 +
                                  (k16 * 16 + bKoff) * 2);
                ldmatrix_x4(b[np * 2][0], b[np * 2][1],
                            b[np * 2 + 1][0], b[np * 2 + 1][1], sb + TILE_B + bo);
            }
#pragma unroll
            for (int mi = 0; mi < 2; ++mi)
#pragma unroll
                for (int ni = 0; ni < 8; ++ni)
                    mma_fp16(acc[mi][ni], a[mi], b[ni]);
        }
    }

    // epilogue (undo WSCALE)
#pragma unroll
    for (int mi = 0; mi < 2; ++mi)
#pragma unroll
        for (int ni = 0; ni < 8; ++ni) {
            int row = bm + warpM * 32 + mi * 16 + (lane >> 2);
            int col = bn + warpN * 64 + ni * 8 + (lane & 3) * 2;
#pragma unroll
            for (int hh = 0; hh < 2; ++hh) {
                int r = row + hh * 8;
                float v0 = acc[mi][ni][hh * 2 + 0] * WSCALE_INV;
                float v1 = acc[mi][ni][hh * 2 + 1] * WSCALE_INV;
                size_t idx = (size_t)r * N + col;
                if (EPI == 2) {
                    __half2 hp = __floats2half2_rn(gelu_f(v0), gelu_f(v1));
                    *(uint32_t*)(Ch + idx) = *(uint32_t*)&hp;
                } else {
                    if (EPI == 1) {
                        float2 rs = *(const float2*)(resid + idx);
                        v0 += bias[col] + rs.x;
                        v1 += bias[col + 1] + rs.y;
                    } else if (EPI == 3) {
                        float2 rs = *(const float2*)(resid + idx);
                        v0 += rs.x; v1 += rs.y;
                    }
                    *(float2*)(Cf + idx) = make_float2(v0, v1);
                }
            }
        }
}

// ------------------------------- launch ---------------------------------------
extern "C" void kernel_launch(void* const* d_in, const int* in_sizes, int n_in,
                              void* d_out, int out_size)
{
    const float* x       = (const float*)d_in[0];
    const float* w_qkv   = (const float*)d_in[1];
    const float* q_scale = (const float*)d_in[2];
    const float* k_scale = (const float*)d_in[3];
    const float* w_out   = (const float*)d_in[4];
    const float* b_out   = (const float*)d_in[5];
    const float* ln1_g   = (const float*)d_in[6];
    const float* ln1_b   = (const float*)d_in[7];
    const float* ff_ln_g = (const float*)d_in[8];
    const float* ff_ln_b = (const float*)d_in[9];
    const float* w_ff1   = (const float*)d_in[10];
    const float* w_ff2   = (const float*)d_in[11];
    float* out = (float*)d_out;

    float *p_qkv, *p_x1;
    __half *p_h, *p_at, *p_f1, *p_wqkv, *p_wout, *p_wff1, *p_wff2;
    cudaGetSymbolAddress((void**)&p_qkv, g_qkv);
    cudaGetSymbolAddress((void**)&p_x1, g_x1);
    cudaGetSymbolAddress((void**)&p_h, g_h);
    cudaGetSymbolAddress((void**)&p_at, g_at);
    cudaGetSymbolAddress((void**)&p_f1, g_f1);
    cudaGetSymbolAddress((void**)&p_wqkv, g_wqkv);
    cudaGetSymbolAddress((void**)&p_wout, g_wout);
    cudaGetSymbolAddress((void**)&p_wff1, g_wff1);
    cudaGetSymbolAddress((void**)&p_wff2, g_wff2);

    cudaFuncSetAttribute(gemm_tc<0>, cudaFuncAttributeMaxDynamicSharedMemorySize, SM_TOTAL);
    cudaFuncSetAttribute(gemm_tc<1>, cudaFuncAttributeMaxDynamicSharedMemorySize, SM_TOTAL);
    cudaFuncSetAttribute(gemm_tc<2>, cudaFuncAttributeMaxDynamicSharedMemorySize, SM_TOTAL);
    cudaFuncSetAttribute(gemm_tc<3>, cudaFuncAttributeMaxDynamicSharedMemorySize, SM_TOTAL);

    // weight converts (fp16 of 512*w)
    wconv_kernel<<<(QKVD * DIMN / 4 + 255) / 256, 256>>>(w_qkv, p_wqkv, QKVD * DIMN / 4);
    wconv_kernel<<<(DIMN * DIMN / 4 + 255) / 256, 256>>>(w_out, p_wout, DIMN * DIMN / 4);
    wconv_kernel<<<(FFD * DIMN / 4 + 255) / 256, 256>>>(w_ff1, p_wff1, FFD * DIMN / 4);
    wconv_kernel<<<(DIMN * FFD / 4 + 255) / 256, 256>>>(w_ff2, p_wff2, DIMN * FFD / 4);

    // 1) h = LN1(x) -> fp16
    ln_kernel<<<NTOK, 128>>>(x, ln1_g, ln1_b, p_h);

    // 2) qkv = h @ w_qkv^T (fp32 out)
    gemm_tc<0><<<dim3(QKVD / 128, NTOK / 128), 256, SM_TOTAL>>>(
        p_h, p_wqkv, NTOK, QKVD, DIMN, p_qkv, nullptr, nullptr, nullptr);

    // 3) l2norm*scale + rotary (in place)
    qkpost_kernel<<<NTOK, 256>>>(p_qkv, q_scale, k_scale);

    // 4) attention -> fp16
    attn_kernel<<<dim3(NW, HEADS, BATCH), 128>>>(p_qkv, p_at);

    // 5) x1 = x + attn @ w_out^T + b_out
    gemm_tc<1><<<dim3(DIMN / 128, NTOK / 128), 256, SM_TOTAL>>>(
        p_at, p_wout, NTOK, DIMN, DIMN, p_x1, nullptr, b_out, x);

    // 6) h = LN2(x1) -> fp16
    ln_kernel<<<NTOK, 128>>>(p_x1, ff_ln_g, ff_ln_b, p_h);

    // 7) ff1 = gelu(h @ w_ff1^T) -> fp16
    gemm_tc<2><<<dim3(FFD / 128, NTOK / 128), 256, SM_TOTAL>>>(
        p_h, p_wff1, NTOK, FFD, DIMN, nullptr, p_f1, nullptr, nullptr);

    // 8) out = x1 + ff1 @ w_ff2^T
    gemm_tc<3><<<dim3(DIMN / 128, NTOK / 128), 256, SM_TOTAL>>>(
        p_f1, p_wff2, NTOK, DIMN, FFD, out, nullptr, nullptr, p_x1);
}

// round 11
// speedup vs baseline: 1.5985x; 1.0102x over previous
#include <cuda_runtime.h>
#include <cuda_bf16.h>
#include <cuda_fp16.h>
#include <stdint.h>
#include <math.h>

#define BATCH   8
#define SEQ     4096
#define DIMN    512
#define HEADS   8
#define DHEAD   64
#define WIN     128
#define NW      (SEQ / WIN)
#define NTOK    (BATCH * SEQ)
#define QKVD    (3 * DIMN)
#define FFD     (4 * DIMN)

#define WSCALE     512.0f            // weights pre-scaled by 512 (exact pow2)
#define WSCALE_INV (1.0f / 512.0f)

// ======================= scratch (static device memory) ========================
__device__ float  g_qkv [(size_t)NTOK * QKVD];
__device__ float  g_x1  [(size_t)NTOK * DIMN];
__device__ __half g_h   [(size_t)NTOK * DIMN];
__device__ __half g_at  [(size_t)NTOK * DIMN];
__device__ __half g_f1  [(size_t)NTOK * FFD];
__device__ __half g_wqkv[QKVD * DIMN];
__device__ __half g_wout[DIMN * DIMN];
__device__ __half g_wff1[FFD * DIMN];
__device__ __half g_wff2[DIMN * FFD];

// ============================ helpers ==========================================
__device__ __forceinline__ uint32_t smem_u32(const void* p) {
    uint32_t a;
    asm("{ .reg .u64 t; cvta.to.shared.u64 t, %1; cvt.u32.u64 %0, t; }" : "=r"(a) : "l"(p));
    return a;
}
#define SWZ(o) ((o) ^ (((o) >> 3) & 0x70))   // SW128 swizzle, 128B rows

__device__ __forceinline__ void cp_async16(uint32_t dst, const void* src) {
    asm volatile("cp.async.cg.shared.global [%0], [%1], 16;" :: "r"(dst), "l"(src));
}
__device__ __forceinline__ void cp_commit() {
    asm volatile("cp.async.commit_group;");
}
template <int N>
__device__ __forceinline__ void cp_wait() {
    asm volatile("cp.async.wait_group %0;" :: "n"(N));
}
__device__ __forceinline__ void ldmatrix_x4(uint32_t& r0, uint32_t& r1,
                                            uint32_t& r2, uint32_t& r3, uint32_t a) {
    asm volatile("ldmatrix.sync.aligned.m8n8.x4.shared.b16 {%0,%1,%2,%3}, [%4];"
                 : "=r"(r0), "=r"(r1), "=r"(r2), "=r"(r3) : "r"(a));
}
__device__ __forceinline__ void mma_fp16(float* c, const uint32_t* a, const uint32_t* b) {
    asm volatile("mma.sync.aligned.m16n8k16.row.col.f32.f16.f16.f32 "
                 "{%0,%1,%2,%3}, {%4,%5,%6,%7}, {%8,%9}, {%0,%1,%2,%3};"
                 : "+f"(c[0]), "+f"(c[1]), "+f"(c[2]), "+f"(c[3])
                 : "r"(a[0]), "r"(a[1]), "r"(a[2]), "r"(a[3]), "r"(b[0]), "r"(b[1]));
}

// ================= LayerNorm -> fp16. block = token =============================
__global__ __launch_bounds__(128) void ln_kernel(const float* __restrict__ in,
                                                 const float* __restrict__ gamma,
                                                 const float* __restrict__ beta,
                                                 __half* __restrict__ oh)
{
    int t = blockIdx.x;
    int tid = threadIdx.x;
    const float4* row = (const float4*)(in + (size_t)t * DIMN);
    float4 v = row[tid];
    float s  = v.x + v.y + v.z + v.w;
    float ss = v.x * v.x + v.y * v.y + v.z * v.z + v.w * v.w;
#pragma unroll
    for (int o = 16; o > 0; o >>= 1) {
        s  += __shfl_xor_sync(0xffffffffu, s, o);
        ss += __shfl_xor_sync(0xffffffffu, ss, o);
    }
    __shared__ float sm[4], sm2[4];
    int w = tid >> 5, lane = tid & 31;
    if (lane == 0) { sm[w] = s; sm2[w] = ss; }
    __syncthreads();
    s  = sm[0] + sm[1] + sm[2] + sm[3];
    ss = sm2[0] + sm2[1] + sm2[2] + sm2[3];
    float mean = s * (1.0f / DIMN);
    float var  = ss * (1.0f / DIMN) - mean * mean;
    float inv  = rsqrtf(var + 1e-5f);
    float4 g = ((const float4*)gamma)[tid];
    float4 b = ((const float4*)beta)[tid];
    float o0 = (v.x - mean) * inv * g.x + b.x;
    float o1 = (v.y - mean) * inv * g.y + b.y;
    float o2 = (v.z - mean) * inv * g.z + b.z;
    float o3 = (v.w - mean) * inv * g.w + b.w;
    __half2 p0 = __floats2half2_rn(o0, o1);
    __half2 p1 = __floats2half2_rn(o2, o3);
    *(uint2*)(oh + (size_t)t * DIMN + tid * 4) = make_uint2(*(uint32_t*)&p0, *(uint32_t*)&p1);
}

// ========= weight convert: fp32 -> fp16 of (512 * w) ============================
__global__ void wconv_kernel(const float* __restrict__ in,
                             __half* __restrict__ oh, int n4)
{
    int i = blockIdx.x * blockDim.x + threadIdx.x;
    if (i >= n4) return;
    float4 v = ((const float4*)in)[i];
    __half2 p0 = __floats2half2_rn(v.x * WSCALE, v.y * WSCALE);
    __half2 p1 = __floats2half2_rn(v.z * WSCALE, v.w * WSCALE);
    ((uint2*)oh)[i] = make_uint2(*(uint32_t*)&p0, *(uint32_t*)&p1);
}

// ========= q/k post: l2norm*scale + rotary (double trig, fp32 phase) ============
__global__ __launch_bounds__(256) void qkpost_kernel(float* __restrict__ qkv,
                                                     const float* __restrict__ qsc,
                                                     const float* __restrict__ ksc)
{
    int t = blockIdx.x;
    int n = t & (SEQ - 1);
    int h = threadIdx.x >> 5;
    int lane = threadIdx.x & 31;

    double invf_d = exp(-(double)(2 * lane) * (9.210340371976184 / 64.0));
    float invf = (float)invf_d;
    float ph = (float)n * invf;
    double sd, cd;
    sincos((double)ph, &sd, &cd);
    float c = (float)cd, s = (float)sd;

    float* base = qkv + (size_t)t * QKVD + h * DHEAD;
    {
        float a = base[lane], b = base[lane + 32];
        float ssq = a * a + b * b;
#pragma unroll
        for (int o = 16; o > 0; o >>= 1) ssq += __shfl_xor_sync(0xffffffffu, ssq, o);
        float inv = 1.0f / fmaxf(sqrtf(ssq), 1e-12f);
        float an = a * inv * qsc[lane];
        float bn = b * inv * qsc[lane + 32];
        base[lane]      = an * c - bn * s;
        base[lane + 32] = bn * c + an * s;
    }
    {
        float* kb = base + DIMN;
        float a = kb[lane], b = kb[lane + 32];
        float ssq = a * a + b * b;
#pragma unroll
        for (int o = 16; o > 0; o >>= 1) ssq += __shfl_xor_sync(0xffffffffu, ssq, o);
        float inv = 1.0f / fmaxf(sqrtf(ssq), 1e-12f);
        float an = a * inv * ksc[lane];
        float bn = b * inv * ksc[lane + 32];
        kb[lane]      = an * c - bn * s;
        kb[lane + 32] = bn * c + an * s;
    }
}

// ====== local-window attention: fixed-offset softmax + 2-key ILP ===============
// Scores bounded (|sc|<=8 after l2norm) -> no running max needed. Two keys per
// iteration double the independent FMA chains (kernel is latency-bound:
// occ ~11%, issue ~50%). Second key predicated at the tail (p2=0).
__global__ __launch_bounds__(128) void attn_kernel(const float* __restrict__ qkv,
                                                   __half* __restrict__ oh)
{
    __shared__ float sK[64][DHEAD];
    __shared__ float sV[64][DHEAD];

    int w = blockIdx.x, h = blockIdx.y, b = blockIdx.z;
    int i = threadIdx.x;
    int tok0 = b * SEQ + w * WIN;
    int tok  = tok0 + i;

    float q[DHEAD];
    {
        const float4* srcQ = (const float4*)(qkv + (size_t)tok * QKVD + h * DHEAD);
#pragma unroll
        for (int d4 = 0; d4 < 16; ++d4) {
            float4 t4 = srcQ[d4];
            q[d4 * 4 + 0] = t4.x; q[d4 * 4 + 1] = t4.y;
            q[d4 * 4 + 2] = t4.z; q[d4 * 4 + 3] = t4.w;
        }
    }

    float acc[DHEAD];
#pragma unroll
    for (int d = 0; d < DHEAD; ++d) acc[d] = 0.f;
    float l = 0.f;

#pragma unroll 1
    for (int c = 0; c < 4; ++c) {
        if (c < 2 && w == 0) continue;

        __syncthreads();
        {
            int r  = i >> 1;
            int f0 = (i & 1) * 8;
            int ktok = tok0 + c * 64 - WIN + r;
            const float4* sk = (const float4*)(qkv + (size_t)ktok * QKVD + DIMN + h * DHEAD);
            const float4* sv = (const float4*)(qkv + (size_t)ktok * QKVD + 2 * DIMN + h * DHEAD);
            float4* dK = (float4*)&sK[r][0];
            float4* dV = (float4*)&sV[r][0];
#pragma unroll
            for (int f = 0; f < 8; ++f) { dK[f0 + f] = sk[f0 + f]; dV[f0 + f] = sv[f0 + f]; }
        }
        __syncthreads();

        int jmax;
        if (c < 2) jmax = 64;
        else {
            jmax = i - (c - 2) * 64 + 1;
            jmax = jmax < 0 ? 0 : (jmax > 64 ? 64 : jmax);
        }
        for (int j = 0; j < jmax; j += 2) {
            int j2 = (j + 1 < 64) ? j + 1 : 63;      // clamped row (value unused if invalid)
            bool has2 = (j + 1 < jmax);
            const float4* kr  = (const float4*)&sK[j][0];
            const float4* kr2 = (const float4*)&sK[j2][0];
            float s0 = 0.f, s1 = 0.f, s2 = 0.f, s3 = 0.f;
            float t0 = 0.f, t1 = 0.f, t2 = 0.f, t3 = 0.f;
#pragma unroll
            for (int d4 = 0; d4 < 16; ++d4) {
                float4 kv  = kr[d4];
                float4 kv2 = kr2[d4];
                s0 += q[d4 * 4 + 0] * kv.x;
                s1 += q[d4 * 4 + 1] * kv.y;
                s2 += q[d4 * 4 + 2] * kv.z;
                s3 += q[d4 * 4 + 3] * kv.w;
                t0 += q[d4 * 4 + 0] * kv2.x;
                t1 += q[d4 * 4 + 1] * kv2.y;
                t2 += q[d4 * 4 + 2] * kv2.z;
                t3 += q[d4 * 4 + 3] * kv2.w;
            }
            float sc  = ((s0 + s1) + (s2 + s3)) * 8.0f;
            float sc2 = ((t0 + t1) + (t2 + t3)) * 8.0f;
            float p  = __expf(sc);
            float p2 = has2 ? __expf(sc2) : 0.f;
            l += p + p2;
            const float4* vr  = (const float4*)&sV[j][0];
            const float4* vr2 = (const float4*)&sV[j2][0];
#pragma unroll
            for (int d4 = 0; d4 < 16; ++d4) {
                float4 vv  = vr[d4];
                float4 vv2 = vr2[d4];
                acc[d4 * 4 + 0] += p * vv.x + p2 * vv2.x;
                acc[d4 * 4 + 1] += p * vv.y + p2 * vv2.y;
                acc[d4 * 4 + 2] += p * vv.z + p2 * vv2.z;
                acc[d4 * 4 + 3] += p * vv.w + p2 * vv2.w;
            }
        }
    }

    float invl = 1.0f / l;
    size_t dstoff = (size_t)tok * DIMN + h * DHEAD;
#pragma unroll
    for (int d4 = 0; d4 < 16; ++d4) {
        __half2 p0 = __floats2half2_rn(acc[d4 * 4 + 0] * invl, acc[d4 * 4 + 1] * invl);
        __half2 p1 = __floats2half2_rn(acc[d4 * 4 + 2] * invl, acc[d4 * 4 + 3] * invl);
        *(uint2*)(oh + dstoff + d4 * 4) = make_uint2(*(uint32_t*)&p0, *(uint32_t*)&p1);
    }
}

// ====== HMMA GEMM fp16, double-buffered cp.async, 2 CTAs/SM ====================
// C = (A @ (512*B)^T) / 512. Stage = 2 tiles (A,B) x 16KB = 32KB; 2 stages =
// 64KB/CTA -> 2 CTAs/SM (128KB < 228KB): cross-CTA overlap AND intra-CTA
// prefetch (the combination R6 couldn't have with 4-tile stages).
// EPI: 0 fp32 | 1 +bias+resid fp32 | 2 gelu -> fp16 | 3 +resid fp32
#define KBLK     64
#define TILE_B   16384
#define STAGE_B  (2 * TILE_B)
#define SM_TOTAL (2 * STAGE_B)

__device__ __forceinline__ float gelu_f(float x)
{
    return 0.5f * x * (1.0f + erff(x * 0.7071067811865476f));
}

template <int EPI>
__global__ __launch_bounds__(256, 2) void gemm_tc(
    const __half* __restrict__ A, const __half* __restrict__ B,
    int M, int N, int K,
    float* __restrict__ Cf, __half* __restrict__ Ch,
    const float* __restrict__ bias, const float* __restrict__ resid)
{
    extern __shared__ char smem[];
    uint32_t sb = smem_u32(smem);
    int tid = threadIdx.x, wid = tid >> 5, lane = tid & 31;
    int warpM = wid & 3, warpN = wid >> 2;
    int bm = blockIdx.y * 128, bn = blockIdx.x * 128;

    float acc[2][8][4];
#pragma unroll
    for (int mi = 0; mi < 2; ++mi)
#pragma unroll
        for (int ni = 0; ni < 8; ++ni)
#pragma unroll
            for (int r = 0; r < 4; ++r) acc[mi][ni][r] = 0.f;

    // ldmatrix lane->address mapping
    int aRow  = lane & 15;
    int aKoff = (lane >> 4) << 3;
    int bRow  = (lane & 7) + ((lane >> 4) << 3);
    int bKoff = ((lane >> 3) & 1) << 3;

    // per-thread load coords: 4 x 16B granules per tile
    int ldRow = tid >> 3, ldC16 = tid & 7;   // granule it: row ldRow + it*32

    int kchunks = K / KBLK;

    // prologue: chunk 0 -> stage 0
#pragma unroll
    for (int tile = 0; tile < 2; ++tile) {
        const __half* src = (tile == 0) ? A : B;
        int rbase = (tile == 0) ? bm : bn;
        uint32_t dstb = sb + tile * TILE_B;
#pragma unroll
        for (int it = 0; it < 4; ++it) {
            int row = ldRow + it * 32;
            cp_async16(dstb + SWZ(row * 128 + ldC16 * 16),
                       src + (size_t)(rbase + row) * K + ldC16 * 8);
        }
    }
    cp_commit();

#pragma unroll 1
    for (int kc = 0; kc < kchunks; ++kc) {
        uint32_t cur = sb + (uint32_t)(kc & 1) * STAGE_B;
        if (kc + 1 < kchunks) {
            uint32_t nxt = sb + (uint32_t)((kc + 1) & 1) * STAGE_B;
            int k0 = (kc + 1) * KBLK;
#pragma unroll
            for (int tile = 0; tile < 2; ++tile) {
                const __half* src = (tile == 0) ? A : B;
                int rbase = (tile == 0) ? bm : bn;
                uint32_t dstb = nxt + tile * TILE_B;
#pragma unroll
                for (int it = 0; it < 4; ++it) {
                    int row = ldRow + it * 32;
                    cp_async16(dstb + SWZ(row * 128 + ldC16 * 16),
                               src + (size_t)(rbase + row) * K + k0 + ldC16 * 8);
                }
            }
            cp_commit();
            cp_wait<1>();     // chunk kc complete; prefetch still in flight
        } else {
            cp_wait<0>();
        }
        __syncthreads();

#pragma unroll
        for (int k16 = 0; k16 < KBLK / 16; ++k16) {
            uint32_t aOff  = SWZ((warpM * 32 + aRow) * 128 + (k16 * 16 + aKoff) * 2);
            uint32_t aOff2 = SWZ((warpM * 32 + 16 + aRow) * 128 + (k16 * 16 + aKoff) * 2);
            uint32_t a[2][4], b[8][2];

            ldmatrix_x4(a[0][0], a[0][1], a[0][2], a[0][3], cur + aOff);
            ldmatrix_x4(a[1][0], a[1][1], a[1][2], a[1][3], cur + aOff2);
#pragma unroll
            for (int np = 0; np < 4; ++np) {
                uint32_t bo = SWZ((warpN * 64 + np * 16 + bRow) * 128 +
                                  (k16 * 16 + bKoff) * 2);
                ldmatrix_x4(b[np * 2][0], b[np * 2][1],
                            b[np * 2 + 1][0], b[np * 2 + 1][1], cur + TILE_B + bo);
            }
#pragma unroll
            for (int mi = 0; mi < 2; ++mi)
#pragma unroll
                for (int ni = 0; ni < 8; ++ni)
                    mma_fp16(acc[mi][ni], a[mi], b[ni]);
        }
        __syncthreads();   // all warps done with 'cur' before refill
    }

    // epilogue (undo WSCALE)
#pragma unroll
    for (int mi = 0; mi < 2; ++mi)
#pragma unroll
        for (int ni = 0; ni < 8; ++ni) {
            int row = bm + warpM * 32 + mi * 16 + (lane >> 2);
            int col = bn + warpN * 64 + ni * 8 + (lane & 3) * 2;
#pragma unroll
            for (int hh = 0; hh < 2; ++hh) {
                int r = row + hh * 8;
                float v0 = acc[mi][ni][hh * 2 + 0] * WSCALE_INV;
                float v1 = acc[mi][ni][hh * 2 + 1] * WSCALE_INV;
                size_t idx = (size_t)r * N + col;
                if (EPI == 2) {
                    __half2 hp = __floats2half2_rn(gelu_f(v0), gelu_f(v1));
                    *(uint32_t*)(Ch + idx) = *(uint32_t*)&hp;
                } else {
                    if (EPI == 1) {
                        float2 rs = *(const float2*)(resid + idx);
                        v0 += bias[col] + rs.x;
                        v1 += bias[col + 1] + rs.y;
                    } else if (EPI == 3) {
                        float2 rs = *(const float2*)(resid + idx);
                        v0 += rs.x; v1 += rs.y;
                    }
                    *(float2*)(Cf + idx) = make_float2(v0, v1);
                }
            }
        }
}

// ------------------------------- launch ---------------------------------------
extern "C" void kernel_launch(void* const* d_in, const int* in_sizes, int n_in,
                              void* d_out, int out_size)
{
    const float* x       = (const float*)d_in[0];
    const float* w_qkv   = (const float*)d_in[1];
    const float* q_scale = (const float*)d_in[2];
    const float* k_scale = (const float*)d_in[3];
    const float* w_out   = (const float*)d_in[4];
    const float* b_out   = (const float*)d_in[5];
    const float* ln1_g   = (const float*)d_in[6];
    const float* ln1_b   = (const float*)d_in[7];
    const float* ff_ln_g = (const float*)d_in[8];
    const float* ff_ln_b = (const float*)d_in[9];
    const float* w_ff1   = (const float*)d_in[10];
    const float* w_ff2   = (const float*)d_in[11];
    float* out = (float*)d_out;

    float *p_qkv, *p_x1;
    __half *p_h, *p_at, *p_f1, *p_wqkv, *p_wout, *p_wff1, *p_wff2;
    cudaGetSymbolAddress((void**)&p_qkv, g_qkv);
    cudaGetSymbolAddress((void**)&p_x1, g_x1);
    cudaGetSymbolAddress((void**)&p_h, g_h);
    cudaGetSymbolAddress((void**)&p_at, g_at);
    cudaGetSymbolAddress((void**)&p_f1, g_f1);
    cudaGetSymbolAddress((void**)&p_wqkv, g_wqkv);
    cudaGetSymbolAddress((void**)&p_wout, g_wout);
    cudaGetSymbolAddress((void**)&p_wff1, g_wff1);
    cudaGetSymbolAddress((void**)&p_wff2, g_wff2);

    cudaFuncSetAttribute(gemm_tc<0>, cudaFuncAttributeMaxDynamicSharedMemorySize, SM_TOTAL);
    cudaFuncSetAttribute(gemm_tc<1>, cudaFuncAttributeMaxDynamicSharedMemorySize, SM_TOTAL);
    cudaFuncSetAttribute(gemm_tc<2>, cudaFuncAttributeMaxDynamicSharedMemorySize, SM_TOTAL);
    cudaFuncSetAttribute(gemm_tc<3>, cudaFuncAttributeMaxDynamicSharedMemorySize, SM_TOTAL);

    // weight converts (fp16 of 512*w)
    wconv_kernel<<<(QKVD * DIMN / 4 + 255) / 256, 256>>>(w_qkv, p_wqkv, QKVD * DIMN / 4);
    wconv_kernel<<<(DIMN * DIMN / 4 + 255) / 256, 256>>>(w_out, p_wout, DIMN * DIMN / 4);
    wconv_kernel<<<(FFD * DIMN / 4 + 255) / 256, 256>>>(w_ff1, p_wff1, FFD * DIMN / 4);
    wconv_kernel<<<(DIMN * FFD / 4 + 255) / 256, 256>>>(w_ff2, p_wff2, DIMN * FFD / 4);

    // 1) h = LN1(x) -> fp16
    ln_kernel<<<NTOK, 128>>>(x, ln1_g, ln1_b, p_h);

    // 2) qkv = h @ w_qkv^T (fp32 out)
    gemm_tc<0><<<dim3(QKVD / 128, NTOK / 128), 256, SM_TOTAL>>>(
        p_h, p_wqkv, NTOK, QKVD, DIMN, p_qkv, nullptr, nullptr, nullptr);

    // 3) l2norm*scale + rotary (in place)
    qkpost_kernel<<<NTOK, 256>>>(p_qkv, q_scale, k_scale);

    // 4) attention -> fp16
    attn_kernel<<<dim3(NW, HEADS, BATCH), 128>>>(p_qkv, p_at);

    // 5) x1 = x + attn @ w_out^T + b_out
    gemm_tc<1><<<dim3(DIMN / 128, NTOK / 128), 256, SM_TOTAL>>>(
        p_at, p_wout, NTOK, DIMN, DIMN, p_x1, nullptr, b_out, x);

    // 6) h = LN2(x1) -> fp16
    ln_kernel<<<NTOK, 128>>>(p_x1, ff_ln_g, ff_ln_b, p_h);

    // 7) ff1 = gelu(h @ w_ff1^T) -> fp16
    gemm_tc<2><<<dim3(FFD / 128, NTOK / 128), 256, SM_TOTAL>>>(
        p_h, p_wff1, NTOK, FFD, DIMN, nullptr, p_f1, nullptr, nullptr);

    // 8) out = x1 + ff1 @ w_ff2^T
    gemm_tc<3><<<dim3(DIMN / 128, NTOK / 128), 256, SM_TOTAL>>>(
        p_f1, p_wff2, NTOK, DIMN, FFD, out, nullptr, nullptr, p_x1);
}

// round 13
// speedup vs baseline: 2.4910x; 1.5583x over previous
#include <cuda_runtime.h>
#include <cuda_bf16.h>
#include <cuda_fp16.h>
#include <stdint.h>
#include <math.h>

#define BATCH   8
#define SEQ     4096
#define DIMN    512
#define HEADS   8
#define DHEAD   64
#define WIN     128
#define NW      (SEQ / WIN)
#define NTOK    (BATCH * SEQ)
#define QKVD    (3 * DIMN)
#define FFD     (4 * DIMN)

#define WSCALE     512.0f            // weights pre-scaled by 512 (exact pow2)
#define WSCALE_INV (1.0f / 512.0f)

// ======================= scratch (static device memory) ========================
__device__ float  g_qkv [(size_t)NTOK * QKVD];
__device__ float  g_x1  [(size_t)NTOK * DIMN];
__device__ __half g_h   [(size_t)NTOK * DIMN];
__device__ __half g_at  [(size_t)NTOK * DIMN];
__device__ __half g_f1  [(size_t)NTOK * FFD];
__device__ __half g_wqkv[QKVD * DIMN];
__device__ __half g_wout[DIMN * DIMN];
__device__ __half g_wff1[FFD * DIMN];
__device__ __half g_wff2[DIMN * FFD];
__device__ float  g_rotc[SEQ * 32];   // rotary cos table [pos][lane]
__device__ float  g_rots[SEQ * 32];   // rotary sin table

// ============================ helpers ==========================================
__device__ __forceinline__ uint32_t smem_u32(const void* p) {
    uint32_t a;
    asm("{ .reg .u64 t; cvta.to.shared.u64 t, %1; cvt.u32.u64 %0, t; }" : "=r"(a) : "l"(p));
    return a;
}
#define SWZ(o) ((o) ^ (((o) >> 3) & 0x70))   // SW128 swizzle, 128B rows

__device__ __forceinline__ void cp_async16(uint32_t dst, const void* src) {
    asm volatile("cp.async.cg.shared.global [%0], [%1], 16;" :: "r"(dst), "l"(src));
}
__device__ __forceinline__ void cp_commit() {
    asm volatile("cp.async.commit_group;");
}
template <int N>
__device__ __forceinline__ void cp_wait() {
    asm volatile("cp.async.wait_group %0;" :: "n"(N));
}
__device__ __forceinline__ void ldmatrix_x4(uint32_t& r0, uint32_t& r1,
                                            uint32_t& r2, uint32_t& r3, uint32_t a) {
    asm volatile("ldmatrix.sync.aligned.m8n8.x4.shared.b16 {%0,%1,%2,%3}, [%4];"
                 : "=r"(r0), "=r"(r1), "=r"(r2), "=r"(r3) : "r"(a));
}
__device__ __forceinline__ void mma_fp16(float* c, const uint32_t* a, const uint32_t* b) {
    asm volatile("mma.sync.aligned.m16n8k16.row.col.f32.f16.f16.f32 "
                 "{%0,%1,%2,%3}, {%4,%5,%6,%7}, {%8,%9}, {%0,%1,%2,%3};"
                 : "+f"(c[0]), "+f"(c[1]), "+f"(c[2]), "+f"(c[3])
                 : "r"(a[0]), "r"(a[1]), "r"(a[2]), "r"(a[3]), "r"(b[0]), "r"(b[1]));
}

// ---- packed fp32x2 (Blackwell): 2 IEEE fp32 ops per instruction ----
__device__ __forceinline__ unsigned long long ffma2(unsigned long long a,
                                                    unsigned long long b,
                                                    unsigned long long c) {
    unsigned long long d;
    asm("fma.rn.f32x2 %0, %1, %2, %3;" : "=l"(d) : "l"(a), "l"(b), "l"(c));
    return d;
}
__device__ __forceinline__ unsigned long long addf2(unsigned long long a,
                                                    unsigned long long b) {
    unsigned long long d;
    asm("add.rn.f32x2 %0, %1, %2;" : "=l"(d) : "l"(a), "l"(b));
    return d;
}
__device__ __forceinline__ float2 unpack2(unsigned long long v) {
    float2 r;
    asm("mov.b64 {%0, %1}, %2;" : "=f"(r.x), "=f"(r.y) : "l"(v));
    return r;
}
__device__ __forceinline__ unsigned long long pack2(float x, float y) {
    unsigned long long v;
    asm("mov.b64 %0, {%1, %2};" : "=l"(v) : "f"(x), "f"(y));
    return v;
}

// ================= LayerNorm -> fp16. block = token =============================
__global__ __launch_bounds__(128) void ln_kernel(const float* __restrict__ in,
                                                 const float* __restrict__ gamma,
                                                 const float* __restrict__ beta,
                                                 __half* __restrict__ oh)
{
    int t = blockIdx.x;
    int tid = threadIdx.x;
    const float4* row = (const float4*)(in + (size_t)t * DIMN);
    float4 v = row[tid];
    float s  = v.x + v.y + v.z + v.w;
    float ss = v.x * v.x + v.y * v.y + v.z * v.z + v.w * v.w;
#pragma unroll
    for (int o = 16; o > 0; o >>= 1) {
        s  += __shfl_xor_sync(0xffffffffu, s, o);
        ss += __shfl_xor_sync(0xffffffffu, ss, o);
    }
    __shared__ float sm[4], sm2[4];
    int w = tid >> 5, lane = tid & 31;
    if (lane == 0) { sm[w] = s; sm2[w] = ss; }
    __syncthreads();
    s  = sm[0] + sm[1] + sm[2] + sm[3];
    ss = sm2[0] + sm2[1] + sm2[2] + sm2[3];
    float mean = s * (1.0f / DIMN);
    float var  = ss * (1.0f / DIMN) - mean * mean;
    float inv  = rsqrtf(var + 1e-5f);
    float4 g = ((const float4*)gamma)[tid];
    float4 b = ((const float4*)beta)[tid];
    float o0 = (v.x - mean) * inv * g.x + b.x;
    float o1 = (v.y - mean) * inv * g.y + b.y;
    float o2 = (v.z - mean) * inv * g.z + b.z;
    float o3 = (v.w - mean) * inv * g.w + b.w;
    __half2 p0 = __floats2half2_rn(o0, o1);
    __half2 p1 = __floats2half2_rn(o2, o3);
    *(uint2*)(oh + (size_t)t * DIMN + tid * 4) = make_uint2(*(uint32_t*)&p0, *(uint32_t*)&p1);
}

// ========= weight convert: fp32 -> fp16 of (512 * w) ============================
__global__ void wconv_kernel(const float* __restrict__ in,
                             __half* __restrict__ oh, int n4)
{
    int i = blockIdx.x * blockDim.x + threadIdx.x;
    if (i >= n4) return;
    float4 v = ((const float4*)in)[i];
    __half2 p0 = __floats2half2_rn(v.x * WSCALE, v.y * WSCALE);
    __half2 p1 = __floats2half2_rn(v.z * WSCALE, v.w * WSCALE);
    ((uint2*)oh)[i] = make_uint2(*(uint32_t*)&p0, *(uint32_t*)&p1);
}

// ========= rotary table: cos/sin of fp32 phase, exact double trig ===============
__global__ void rotary_kernel(float* __restrict__ rc, float* __restrict__ rs)
{
    int idx = blockIdx.x * blockDim.x + threadIdx.x;   // SEQ*32
    int n = idx >> 5, lane = idx & 31;
    double invf_d = exp(-(double)(2 * lane) * (9.210340371976184 / 64.0));
    float ph = (float)n * (float)invf_d;               // fp32 phase (matches ref)
    double sd, cd;
    sincos((double)ph, &sd, &cd);
    rc[idx] = (float)cd;
    rs[idx] = (float)sd;
}

// ========= q/k post: l2norm*scale + rotary (table lookup) =======================
__global__ __launch_bounds__(256) void qkpost_kernel(float* __restrict__ qkv,
                                                     const float* __restrict__ qsc,
                                                     const float* __restrict__ ksc,
                                                     const float* __restrict__ rc,
                                                     const float* __restrict__ rs)
{
    int t = blockIdx.x;
    int n = t & (SEQ - 1);
    int h = threadIdx.x >> 5;
    int lane = threadIdx.x & 31;

    float c = rc[n * 32 + lane];
    float s = rs[n * 32 + lane];

    float* base = qkv + (size_t)t * QKVD + h * DHEAD;
    {
        float a = base[lane], b = base[lane + 32];
        float ssq = a * a + b * b;
#pragma unroll
        for (int o = 16; o > 0; o >>= 1) ssq += __shfl_xor_sync(0xffffffffu, ssq, o);
        float inv = 1.0f / fmaxf(sqrtf(ssq), 1e-12f);
        float an = a * inv * qsc[lane];
        float bn = b * inv * qsc[lane + 32];
        base[lane]      = an * c - bn * s;
        base[lane + 32] = bn * c + an * s;
    }
    {
        float* kb = base + DIMN;
        float a = kb[lane], b = kb[lane + 32];
        float ssq = a * a + b * b;
#pragma unroll
        for (int o = 16; o > 0; o >>= 1) ssq += __shfl_xor_sync(0xffffffffu, ssq, o);
        float inv = 1.0f / fmaxf(sqrtf(ssq), 1e-12f);
        float an = a * inv * ksc[lane];
        float bn = b * inv * ksc[lane + 32];
        kb[lane]      = an * c - bn * s;
        kb[lane + 32] = bn * c + an * s;
    }
}

// ====== local-window attention: fixed-offset softmax + packed f32x2 math =======
// 64 dims = 16 ulonglong2 per row (R12 bug: loops ran 8 -> half the head dim).
__global__ __launch_bounds__(128) void attn_kernel(const float* __restrict__ qkv,
                                                   __half* __restrict__ oh)
{
    __shared__ float sK[64][DHEAD];
    __shared__ float sV[64][DHEAD];

    int w = blockIdx.x, h = blockIdx.y, b = blockIdx.z;
    int i = threadIdx.x;
    int tok0 = b * SEQ + w * WIN;
    int tok  = tok0 + i;

    unsigned long long q2[32];   // 64 dims as 32 packed fp32 pairs
    {
        const ulonglong2* srcQ = (const ulonglong2*)(qkv + (size_t)tok * QKVD + h * DHEAD);
#pragma unroll
        for (int d = 0; d < 16; ++d) {
            ulonglong2 t2 = srcQ[d];
            q2[2 * d] = t2.x; q2[2 * d + 1] = t2.y;
        }
    }

    unsigned long long acc2[32];
#pragma unroll
    for (int d = 0; d < 32; ++d) acc2[d] = 0ull;   // (+0.0f, +0.0f)
    float l = 0.f;

#pragma unroll 1
    for (int c = 0; c < 4; ++c) {
        if (c < 2 && w == 0) continue;

        __syncthreads();
        {
            int r  = i >> 1;
            int f0 = (i & 1) * 8;
            int ktok = tok0 + c * 64 - WIN + r;
            const float4* sk = (const float4*)(qkv + (size_t)ktok * QKVD + DIMN + h * DHEAD);
            const float4* sv = (const float4*)(qkv + (size_t)ktok * QKVD + 2 * DIMN + h * DHEAD);
            float4* dK = (float4*)&sK[r][0];
            float4* dV = (float4*)&sV[r][0];
#pragma unroll
            for (int f = 0; f < 8; ++f) { dK[f0 + f] = sk[f0 + f]; dV[f0 + f] = sv[f0 + f]; }
        }
        __syncthreads();

        int jmax;
        if (c < 2) jmax = 64;
        else {
            jmax = i - (c - 2) * 64 + 1;
            jmax = jmax < 0 ? 0 : (jmax > 64 ? 64 : jmax);
        }
        for (int j = 0; j < jmax; ++j) {
            const ulonglong2* kr = (const ulonglong2*)&sK[j][0];
            unsigned long long s0 = 0ull, s1 = 0ull, s2 = 0ull, s3 = 0ull;
#pragma unroll
            for (int d = 0; d < 16; ++d) {           // 16 ulonglong2 = 64 floats
                ulonglong2 kk = kr[d];
                if (d & 1) {
                    s2 = ffma2(q2[2 * d],     kk.x, s2);
                    s3 = ffma2(q2[2 * d + 1], kk.y, s3);
                } else {
                    s0 = ffma2(q2[2 * d],     kk.x, s0);
                    s1 = ffma2(q2[2 * d + 1], kk.y, s1);
                }
            }
            unsigned long long tsum = addf2(addf2(s0, s1), addf2(s2, s3));
            float2 tf = unpack2(tsum);
            float sc = (tf.x + tf.y) * 8.0f;   // QK_SCALE; |sc|<=8 (l2-normed q,k)
            float p  = __expf(sc);             // no overflow; offset-free softmax
            l += p;
            unsigned long long pp = pack2(p, p);
            const ulonglong2* vr = (const ulonglong2*)&sV[j][0];
#pragma unroll
            for (int d = 0; d < 16; ++d) {           // full 64 dims
                ulonglong2 vv = vr[d];
                acc2[2 * d]     = ffma2(pp, vv.x, acc2[2 * d]);
                acc2[2 * d + 1] = ffma2(pp, vv.y, acc2[2 * d + 1]);
            }
        }
    }

    float invl = 1.0f / l;
    size_t dstoff = (size_t)tok * DIMN + h * DHEAD;
#pragma unroll
    for (int g = 0; g < 8; ++g) {
        uint32_t hp[4];
#pragma unroll
        for (int k = 0; k < 4; ++k) {
            float2 f = unpack2(acc2[g * 4 + k]);
            __half2 hh = __floats2half2_rn(f.x * invl, f.y * invl);
            hp[k] = *(uint32_t*)&hh;
        }
        *(uint4*)(oh + dstoff + g * 8) = make_uint4(hp[0], hp[1], hp[2], hp[3]);
    }
}

// ====== HMMA GEMM fp16, double-buffered cp.async, 2 CTAs/SM (R11 config) =======
#define KBLK     64
#define TILE_B   16384
#define STAGE_B  (2 * TILE_B)
#define SM_TOTAL (2 * STAGE_B)

__device__ __forceinline__ float gelu_f(float x)
{
    return 0.5f * x * (1.0f + erff(x * 0.7071067811865476f));
}

template <int EPI>   // 0 fp32 | 1 +bias+resid fp32 | 2 gelu->fp16 | 3 +resid fp32
__global__ __launch_bounds__(256, 2) void gemm_tc(
    const __half* __restrict__ A, const __half* __restrict__ B,
    int M, int N, int K,
    float* __restrict__ Cf, __half* __restrict__ Ch,
    const float* __restrict__ bias, const float* __restrict__ resid)
{
    extern __shared__ char smem[];
    uint32_t sb = smem_u32(smem);
    int tid = threadIdx.x, wid = tid >> 5, lane = tid & 31;
    int warpM = wid & 3, warpN = wid >> 2;
    int bm = blockIdx.y * 128, bn = blockIdx.x * 128;

    float acc[2][8][4];
#pragma unroll
    for (int mi = 0; mi < 2; ++mi)
#pragma unroll
        for (int ni = 0; ni < 8; ++ni)
#pragma unroll
            for (int r = 0; r < 4; ++r) acc[mi][ni][r] = 0.f;

    int aRow  = lane & 15;
    int aKoff = (lane >> 4) << 3;
    int bRow  = (lane & 7) + ((lane >> 4) << 3);
    int bKoff = ((lane >> 3) & 1) << 3;

    int ldRow = tid >> 3, ldC16 = tid & 7;

    int kchunks = K / KBLK;

#pragma unroll
    for (int tile = 0; tile < 2; ++tile) {
        const __half* src = (tile == 0) ? A : B;
        int rbase = (tile == 0) ? bm : bn;
        uint32_t dstb = sb + tile * TILE_B;
#pragma unroll
        for (int it = 0; it < 4; ++it) {
            int row = ldRow + it * 32;
            cp_async16(dstb + SWZ(row * 128 + ldC16 * 16),
                       src + (size_t)(rbase + row) * K + ldC16 * 8);
        }
    }
    cp_commit();

#pragma unroll 1
    for (int kc = 0; kc < kchunks; ++kc) {
        uint32_t cur = sb + (uint32_t)(kc & 1) * STAGE_B;
        if (kc + 1 < kchunks) {
            uint32_t nxt = sb + (uint32_t)((kc + 1) & 1) * STAGE_B;
            int k0 = (kc + 1) * KBLK;
#pragma unroll
            for (int tile = 0; tile < 2; ++tile) {
                const __half* src = (tile == 0) ? A : B;
                int rbase = (tile == 0) ? bm : bn;
                uint32_t dstb = nxt + tile * TILE_B;
#pragma unroll
                for (int it = 0; it < 4; ++it) {
                    int row = ldRow + it * 32;
                    cp_async16(dstb + SWZ(row * 128 + ldC16 * 16),
                               src + (size_t)(rbase + row) * K + k0 + ldC16 * 8);
                }
            }
            cp_commit();
            cp_wait<1>();
        } else {
            cp_wait<0>();
        }
        __syncthreads();

#pragma unroll
        for (int k16 = 0; k16 < KBLK / 16; ++k16) {
            uint32_t aOff  = SWZ((warpM * 32 + aRow) * 128 + (k16 * 16 + aKoff) * 2);
            uint32_t aOff2 = SWZ((warpM * 32 + 16 + aRow) * 128 + (k16 * 16 + aKoff) * 2);
            uint32_t a[2][4], b[8][2];

            ldmatrix_x4(a[0][0], a[0][1], a[0][2], a[0][3], cur + aOff);
            ldmatrix_x4(a[1][0], a[1][1], a[1][2], a[1][3], cur + aOff2);
#pragma unroll
            for (int np = 0; np < 4; ++np) {
                uint32_t bo = SWZ((warpN * 64 + np * 16 + bRow) * 128 +
                                  (k16 * 16 + bKoff) * 2);
                ldmatrix_x4(b[np * 2][0], b[np * 2][1],
                            b[np * 2 + 1][0], b[np * 2 + 1][1], cur + TILE_B + bo);
            }
#pragma unroll
            for (int mi = 0; mi < 2; ++mi)
#pragma unroll
                for (int ni = 0; ni < 8; ++ni)
                    mma_fp16(acc[mi][ni], a[mi], b[ni]);
        }
        __syncthreads();
    }

#pragma unroll
    for (int mi = 0; mi < 2; ++mi)
#pragma unroll
        for (int ni = 0; ni < 8; ++ni) {
            int row = bm + warpM * 32 + mi * 16 + (lane >> 2);
            int col = bn + warpN * 64 + ni * 8 + (lane & 3) * 2;
#pragma unroll
            for (int hh = 0; hh < 2; ++hh) {
                int r = row + hh * 8;
                float v0 = acc[mi][ni][hh * 2 + 0] * WSCALE_INV;
                float v1 = acc[mi][ni][hh * 2 + 1] * WSCALE_INV;
                size_t idx = (size_t)r * N + col;
                if (EPI == 2) {
                    __half2 hp = __floats2half2_rn(gelu_f(v0), gelu_f(v1));
                    *(uint32_t*)(Ch + idx) = *(uint32_t*)&hp;
                } else {
                    if (EPI == 1) {
                        float2 rs = *(const float2*)(resid + idx);
                        v0 += bias[col] + rs.x;
                        v1 += bias[col + 1] + rs.y;
                    } else if (EPI == 3) {
                        float2 rs = *(const float2*)(resid + idx);
                        v0 += rs.x; v1 += rs.y;
                    }
                    *(float2*)(Cf + idx) = make_float2(v0, v1);
                }
            }
        }
}

// ------------------------------- launch ---------------------------------------
extern "C" void kernel_launch(void* const* d_in, const int* in_sizes, int n_in,
                              void* d_out, int out_size)
{
    const float* x       = (const float*)d_in[0];
    const float* w_qkv   = (const float*)d_in[1];
    const float* q_scale = (const float*)d_in[2];
    const float* k_scale = (const float*)d_in[3];
    const float* w_out   = (const float*)d_in[4];
    const float* b_out   = (const float*)d_in[5];
    const float* ln1_g   = (const float*)d_in[6];
    const float* ln1_b   = (const float*)d_in[7];
    const float* ff_ln_g = (const float*)d_in[8];
    const float* ff_ln_b = (const float*)d_in[9];
    const float* w_ff1   = (const float*)d_in[10];
    const float* w_ff2   = (const float*)d_in[11];
    float* out = (float*)d_out;

    float *p_qkv, *p_x1, *p_rotc, *p_rots;
    __half *p_h, *p_at, *p_f1, *p_wqkv, *p_wout, *p_wff1, *p_wff2;
    cudaGetSymbolAddress((void**)&p_qkv, g_qkv);
    cudaGetSymbolAddress((void**)&p_x1, g_x1);
    cudaGetSymbolAddress((void**)&p_rotc, g_rotc);
    cudaGetSymbolAddress((void**)&p_rots, g_rots);
    cudaGetSymbolAddress((void**)&p_h, g_h);
    cudaGetSymbolAddress((void**)&p_at, g_at);
    cudaGetSymbolAddress((void**)&p_f1, g_f1);
    cudaGetSymbolAddress((void**)&p_wqkv, g_wqkv);
    cudaGetSymbolAddress((void**)&p_wout, g_wout);
    cudaGetSymbolAddress((void**)&p_wff1, g_wff1);
    cudaGetSymbolAddress((void**)&p_wff2, g_wff2);

    cudaFuncSetAttribute(gemm_tc<0>, cudaFuncAttributeMaxDynamicSharedMemorySize, SM_TOTAL);
    cudaFuncSetAttribute(gemm_tc<1>, cudaFuncAttributeMaxDynamicSharedMemorySize, SM_TOTAL);
    cudaFuncSetAttribute(gemm_tc<2>, cudaFuncAttributeMaxDynamicSharedMemorySize, SM_TOTAL);
    cudaFuncSetAttribute(gemm_tc<3>, cudaFuncAttributeMaxDynamicSharedMemorySize, SM_TOTAL);

    // rotary table + weight converts (independent of LN/GEMM0 chain)
    rotary_kernel<<<(SEQ * 32) / 256, 256>>>(p_rotc, p_rots);
    wconv_kernel<<<(QKVD * DIMN / 4 + 255) / 256, 256>>>(w_qkv, p_wqkv, QKVD * DIMN / 4);
    wconv_kernel<<<(DIMN * DIMN / 4 + 255) / 256, 256>>>(w_out, p_wout, DIMN * DIMN / 4);
    wconv_kernel<<<(FFD * DIMN / 4 + 255) / 256, 256>>>(w_ff1, p_wff1, FFD * DIMN / 4);
    wconv_kernel<<<(DIMN * FFD / 4 + 255) / 256, 256>>>(w_ff2, p_wff2, DIMN * FFD / 4);

    // 1) h = LN1(x) -> fp16
    ln_kernel<<<NTOK, 128>>>(x, ln1_g, ln1_b, p_h);

    // 2) qkv = h @ w_qkv^T (fp32 out)
    gemm_tc<0><<<dim3(QKVD / 128, NTOK / 128), 256, SM_TOTAL>>>(
        p_h, p_wqkv, NTOK, QKVD, DIMN, p_qkv, nullptr, nullptr, nullptr);

    // 3) l2norm*scale + rotary (table lookup, in place)
    qkpost_kernel<<<NTOK, 256>>>(p_qkv, q_scale, k_scale, p_rotc, p_rots);

    // 4) attention -> fp16
    attn_kernel<<<dim3(NW, HEADS, BATCH), 128>>>(p_qkv, p_at);

    // 5) x1 = x + attn @ w_out^T + b_out
    gemm_tc<1><<<dim3(DIMN / 128, NTOK / 128), 256, SM_TOTAL>>>(
        p_at, p_wout, NTOK, DIMN, DIMN, p_x1, nullptr, b_out, x);

    // 6) h = LN2(x1) -> fp16
    ln_kernel<<<NTOK, 128>>>(p_x1, ff_ln_g, ff_ln_b, p_h);

    // 7) ff1 = gelu(h @ w_ff1^T) -> fp16
    gemm_tc<2><<<dim3(FFD / 128, NTOK / 128), 256, SM_TOTAL>>>(
        p_h, p_wff1, NTOK, FFD, DIMN, nullptr, p_f1, nullptr, nullptr);

    // 8) out = x1 + ff1 @ w_ff2^T
    gemm_tc<3><<<dim3(DIMN / 128, NTOK / 128), 256, SM_TOTAL>>>(
        p_f1, p_wff2, NTOK, DIMN, FFD, out, nullptr, nullptr, p_x1);
}